// round 14
// baseline (speedup 1.0000x reference)
#include <cuda_runtime.h>
#include <cuda_fp16.h>
#include <math.h>
#include <stdint.h>

#define N_NODES 50000
#define N_EDGES 800000
#define DIM 128

typedef unsigned long long ull;
typedef unsigned short u16;

__device__ float g_h[(size_t)N_NODES * DIM];
__device__ float g_h1[(size_t)N_NODES * 256];
__device__ float g_PQ[(size_t)N_NODES * 256];
__device__ float4 g_edge[(size_t)N_EDGES];
__device__ int g_cnt[N_NODES];
__device__ int g_off[N_NODES];
__device__ int g_cur[N_NODES];
__device__ float g_bnsum[512];
__device__ __align__(16) u16 g_B1h[128 * 264];
__device__ __align__(16) u16 g_B3h[128 * 264];
__device__ __align__(16) u16 g_B2h[256 * 136];

__device__ __forceinline__ uint32_t smem_u32(const void* p) {
    uint32_t a;
    asm("{ .reg .u64 t; cvta.to.shared.u64 t, %1; cvt.u32.u64 %0, t; }" : "=r"(a) : "l"(p));
    return a;
}
__device__ __forceinline__ void ldmx4(uint32_t* r, uint32_t addr) {
    asm volatile("ldmatrix.sync.aligned.m8n8.x4.shared.b16 {%0,%1,%2,%3}, [%4];"
        : "=r"(r[0]), "=r"(r[1]), "=r"(r[2]), "=r"(r[3]) : "r"(addr));
}
__device__ __forceinline__ void ldmx4t(uint32_t* r, uint32_t addr) {
    asm volatile("ldmatrix.sync.aligned.m8n8.x4.trans.shared.b16 {%0,%1,%2,%3}, [%4];"
        : "=r"(r[0]), "=r"(r[1]), "=r"(r[2]), "=r"(r[3]) : "r"(addr));
}
__device__ __forceinline__ void mma16816(float* c, const uint32_t* a, uint32_t b0, uint32_t b1) {
    asm volatile("mma.sync.aligned.m16n8k16.row.col.f32.f16.f16.f32 "
        "{%0,%1,%2,%3}, {%4,%5,%6,%7}, {%8,%9}, {%0,%1,%2,%3};"
        : "+f"(c[0]), "+f"(c[1]), "+f"(c[2]), "+f"(c[3])
        : "r"(a[0]), "r"(a[1]), "r"(a[2]), "r"(a[3]), "r"(b0), "r"(b1));
}
__device__ __forceinline__ void split2(float a, float b, uint32_t& uh, uint32_t& ul) {
    __half h0 = __float2half_rn(a), h1 = __float2half_rn(b);
    float r0 = a - __half2float(h0), r1 = b - __half2float(h1);
    __half l0 = __float2half_rn(r0), l1 = __float2half_rn(r1);
    uh = (uint32_t)(*(u16*)&h0) | ((uint32_t)(*(u16*)&h1) << 16);
    ul = (uint32_t)(*(u16*)&l0) | ((uint32_t)(*(u16*)&l1) << 16);
}
__device__ __forceinline__ float fgelu(float v) {
    float x = fabsf(v) * 0.70710678118654752f;
    float t = __fdividef(1.0f, fmaf(0.3275911f, x, 1.0f));
    float poly = t * fmaf(t, fmaf(t, fmaf(t, fmaf(t, 1.061405429f, -1.453152027f),
                  1.421413741f), -0.284496736f), 0.254829592f);
    float ex = __expf(-x * x);
    float erf_abs = fmaf(-poly, ex, 1.0f);
    float erf_v = copysignf(erf_abs, v);
    return 0.5f * v * (1.0f + erf_v);
}

#define CTRL 8192
#define ASTR 272
#define OFF_AH CTRL
#define OFF_AL (OFF_AH + 128 * ASTR)
#define OFF_BH (OFF_AL + 128 * ASTR)
#define SM_TC256 (OFF_BH + 67584)
#define SM_MLP2  (OFF_BH + 69632)

__global__ void __launch_bounds__(256) prep_all(
    const float* __restrict__ W1, const float* __restrict__ We, const float* __restrict__ W2)
{
    int b = blockIdx.x;
    if (b >= 384) {
        int i = (b - 384) * 256 + threadIdx.x;
        if (i < N_NODES) g_cnt[i] = 0;
        return;
    }
    int li = (b % 128) * 256 + threadIdx.x;
    if (b < 256) {
        int j = li >> 7, k = li & 127;
        float v = (b < 128) ? W1[j * 128 + k]
                : ((j < 128) ? We[j * 256 + k] : We[(j - 128) * 256 + 128 + k]);
        __half hb = __float2half_rn(v);
        u16* Bh = (b < 128) ? g_B1h : g_B3h;
        Bh[k * 264 + j] = *(u16*)&hb;
    } else {
        int j = li >> 8, k = li & 255;
        __half hb = __float2half_rn(W2[j * 256 + k]);
        g_B2h[k * 136 + j] = *(u16*)&hb;
    }
}

__global__ void __launch_bounds__(256) hist(const int* __restrict__ dst)
{
    int e = blockIdx.x * 256 + threadIdx.x;
    if (e < N_EDGES) atomicAdd(&g_cnt[dst[e]], 1);
}

__global__ void __launch_bounds__(1024) scan50k()
{
    __shared__ int wsum[32];
    __shared__ int sh_carry;
    int tid = threadIdx.x, lane = tid & 31, w = tid >> 5;
    if (tid == 0) sh_carry = 0;
    __syncthreads();
    for (int base = 0; base < N_NODES; base += 1024) {
        int i = base + tid;
        int v = (i < N_NODES) ? g_cnt[i] : 0;
        int x = v;
#pragma unroll
        for (int o = 1; o < 32; o <<= 1) { int y = __shfl_up_sync(~0u, x, o); if (lane >= o) x += y; }
        if (lane == 31) wsum[w] = x;
        __syncthreads();
        if (w == 0) {
            int s = wsum[lane];
#pragma unroll
            for (int o = 1; o < 32; o <<= 1) { int y = __shfl_up_sync(~0u, s, o); if (lane >= o) s += y; }
            wsum[lane] = s;
        }
        __syncthreads();
        int warp_excl = (w == 0) ? 0 : wsum[w - 1];
        int carry = sh_carry;
        int excl = carry + warp_excl + x - v;
        if (i < N_NODES) { g_off[i] = excl; g_cur[i] = excl; }
        __syncthreads();
        if (tid == 1023) sh_carry = carry + wsum[31];
        __syncthreads();
    }
}

__global__ void __launch_bounds__(256) scatter(
    const int* __restrict__ src, const int* __restrict__ dst, const float* __restrict__ ea)
{
    int e = blockIdx.x * 256 + threadIdx.x;
    if (e >= N_EDGES) return;
    int d = dst[e];
    int pos = atomicAdd(&g_cur[d], 1);
    g_edge[pos] = make_float4(__int_as_float(src[e]), ea[e], __int_as_float(e), 0.f);
}

__global__ void __launch_bounds__(256) aggregate(
    const float* __restrict__ x, const float* __restrict__ W_edge, const float* __restrict__ tptr)
{
    int gw = (blockIdx.x * 256 + threadIdx.x) >> 5;
    int lane = threadIdx.x & 31;
    if (gw >= N_NODES) return;
    const float t = tptr[0];
    int half = lane >> 4, cl = lane & 15;
    int c0 = cl * 8;
    float4 w0 = *(const float4*)&W_edge[c0];
    float4 w1 = *(const float4*)&W_edge[c0 + 4];

    int beg = g_off[gw];
    int end = (gw == N_NODES - 1) ? N_EDGES : g_off[gw + 1];

    float4 aE0 = make_float4(0.f, 0.f, 0.f, 0.f), aE1 = aE0;
    float4 aM0 = aE0, aM1 = aE0;

    for (int b = beg; b < end; b += 32) {
        int j = b + lane;
        int sl = 0; float af = 0.f;
        if (j < end) { float4 e4 = g_edge[j]; sl = __float_as_int(e4.x); af = e4.y; }
        int cnt = min(32, end - b);
        for (int q = 0; q < cnt; q += 2) {
            int idx = q + half;
            int s_e   = __shfl_sync(0xffffffffu, sl, idx);
            float a_e = __shfl_sync(0xffffffffu, af, idx);
            float vf = (idx < cnt) ? 1.f : 0.f;
            const float4* xp = (const float4*)&x[(size_t)s_e * DIM + c0];
            float4 x0 = xp[0], x1 = xp[1];
            float m0 = fmaxf(fmaf(a_e, w0.x, x0.x), 0.f) + 1e-7f;
            float m1 = fmaxf(fmaf(a_e, w0.y, x0.y), 0.f) + 1e-7f;
            float m2 = fmaxf(fmaf(a_e, w0.z, x0.z), 0.f) + 1e-7f;
            float m3 = fmaxf(fmaf(a_e, w0.w, x0.w), 0.f) + 1e-7f;
            float m4 = fmaxf(fmaf(a_e, w1.x, x1.x), 0.f) + 1e-7f;
            float m5 = fmaxf(fmaf(a_e, w1.y, x1.y), 0.f) + 1e-7f;
            float m6 = fmaxf(fmaf(a_e, w1.z, x1.z), 0.f) + 1e-7f;
            float m7 = fmaxf(fmaf(a_e, w1.w, x1.w), 0.f) + 1e-7f;
            float e0 = __expf(m0 * t) * vf, e1 = __expf(m1 * t) * vf;
            float e2 = __expf(m2 * t) * vf, e3 = __expf(m3 * t) * vf;
            float e4 = __expf(m4 * t) * vf, e5 = __expf(m5 * t) * vf;
            float e6 = __expf(m6 * t) * vf, e7 = __expf(m7 * t) * vf;
            aE0.x += e0; aE0.y += e1; aE0.z += e2; aE0.w += e3;
            aE1.x += e4; aE1.y += e5; aE1.z += e6; aE1.w += e7;
            aM0.x = fmaf(m0, e0, aM0.x); aM0.y = fmaf(m1, e1, aM0.y);
            aM0.z = fmaf(m2, e2, aM0.z); aM0.w = fmaf(m3, e3, aM0.w);
            aM1.x = fmaf(m4, e4, aM1.x); aM1.y = fmaf(m5, e5, aM1.y);
            aM1.z = fmaf(m6, e6, aM1.z); aM1.w = fmaf(m7, e7, aM1.w);
        }
    }
    aE0.x += __shfl_xor_sync(~0u, aE0.x, 16); aE0.y += __shfl_xor_sync(~0u, aE0.y, 16);
    aE0.z += __shfl_xor_sync(~0u, aE0.z, 16); aE0.w += __shfl_xor_sync(~0u, aE0.w, 16);
    aE1.x += __shfl_xor_sync(~0u, aE1.x, 16); aE1.y += __shfl_xor_sync(~0u, aE1.y, 16);
    aE1.z += __shfl_xor_sync(~0u, aE1.z, 16); aE1.w += __shfl_xor_sync(~0u, aE1.w, 16);
    aM0.x += __shfl_xor_sync(~0u, aM0.x, 16); aM0.y += __shfl_xor_sync(~0u, aM0.y, 16);
    aM0.z += __shfl_xor_sync(~0u, aM0.z, 16); aM0.w += __shfl_xor_sync(~0u, aM0.w, 16);
    aM1.x += __shfl_xor_sync(~0u, aM1.x, 16); aM1.y += __shfl_xor_sync(~0u, aM1.y, 16);
    aM1.z += __shfl_xor_sync(~0u, aM1.z, 16); aM1.w += __shfl_xor_sync(~0u, aM1.w, 16);

    if (half == 0) {
        float4 xn0 = *(const float4*)&x[(size_t)gw * DIM + c0];
        float4 xn1 = *(const float4*)&x[(size_t)gw * DIM + c0 + 4];
        float4 h0, h1;
        h0.x = aM0.x / (aE0.x + 1e-16f) + xn0.x;
        h0.y = aM0.y / (aE0.y + 1e-16f) + xn0.y;
        h0.z = aM0.z / (aE0.z + 1e-16f) + xn0.z;
        h0.w = aM0.w / (aE0.w + 1e-16f) + xn0.w;
        h1.x = aM1.x / (aE1.x + 1e-16f) + xn1.x;
        h1.y = aM1.y / (aE1.y + 1e-16f) + xn1.y;
        h1.z = aM1.z / (aE1.z + 1e-16f) + xn1.z;
        h1.w = aM1.w / (aE1.w + 1e-16f) + xn1.w;
        float4* hp = (float4*)&g_h[(size_t)gw * DIM + c0];
        hp[0] = h0;
        hp[1] = h1;
    }
}

__global__ void __launch_bounds__(512, 1) tc256(
    const float* __restrict__ in, const u16* __restrict__ Bh, float* __restrict__ out)
{
    extern __shared__ __align__(16) char sm[];
    uint32_t sb = smem_u32(sm);
    int tid = threadIdx.x, wid = tid >> 5, lane = tid & 31;
    int row0 = blockIdx.x * 128;

    {
        const float4* bh = (const float4*)Bh;
        float4* sh = (float4*)(sm + OFF_BH);
        for (int i = tid; i < 4224; i += 512) sh[i] = bh[i];
    }
    for (int i = tid; i < 128 * 64; i += 512) {
        int r = i >> 6, k2 = (i & 63) << 1;
        int row = row0 + r;
        float2 hv = make_float2(0.f, 0.f);
        if (row < N_NODES) hv = *(const float2*)&in[(size_t)row * 128 + k2];
        uint32_t uh, ul;
        split2(hv.x, hv.y, uh, ul);
        *(uint32_t*)(sm + OFF_AH + r * ASTR + k2 * 2) = uh;
        *(uint32_t*)(sm + OFF_AL + r * ASTR + k2 * 2) = ul;
    }
    __syncthreads();

    int mrow0 = (wid & 7) * 16, nh = wid >> 3;
    uint32_t aRow = mrow0 + (lane & 7) + ((lane >> 3) & 1) * 8;
    uint32_t aAddrH = sb + OFF_AH + aRow * ASTR + (lane >> 4) * 16;
    uint32_t aAddrL = aAddrH + (OFF_AL - OFF_AH);
    uint32_t bLaneRow = (lane & 7) + ((lane >> 3) & 1) * 8;
    uint32_t bLaneN = ((lane >> 4) & 1) * 16 + nh * 256;

    float c[16][4];
#pragma unroll
    for (int t = 0; t < 16; t++)
#pragma unroll
        for (int q = 0; q < 4; q++) c[t][q] = 0.f;

#pragma unroll
    for (int kst = 0; kst < 8; kst++) {
        uint32_t ah[4], al[4];
        ldmx4(ah, aAddrH + kst * 32);
        ldmx4(al, aAddrL + kst * 32);
        uint32_t bAddr = sb + OFF_BH + (kst * 16 + bLaneRow) * 528 + bLaneN;
#pragma unroll
        for (int tp = 0; tp < 8; tp++) {
            uint32_t bh[4];
            ldmx4t(bh, bAddr + tp * 32);
            mma16816(c[2 * tp],     ah, bh[0], bh[1]);
            mma16816(c[2 * tp],     al, bh[0], bh[1]);
            mma16816(c[2 * tp + 1], ah, bh[2], bh[3]);
            mma16816(c[2 * tp + 1], al, bh[2], bh[3]);
        }
    }

    int rbase = row0 + mrow0 + (lane >> 2);
    int cbase = nh * 128 + (lane & 3) * 2;
#pragma unroll
    for (int t = 0; t < 16; t++) {
        int n0 = cbase + t * 8;
        if (rbase < N_NODES)     *(float2*)&out[(size_t)rbase * 256 + n0]       = make_float2(c[t][0], c[t][1]);
        if (rbase + 8 < N_NODES) *(float2*)&out[(size_t)(rbase + 8) * 256 + n0] = make_float2(c[t][2], c[t][3]);
    }
}

__global__ void __launch_bounds__(256) bn_reduce()
{
    int t = threadIdx.x;
    int r0 = blockIdx.x * 250, r1 = min(r0 + 250, N_NODES);
    float s = 0.f, q = 0.f;
    for (int row = r0; row < r1; row++) {
        float v = g_h1[(size_t)row * 256 + t];
        s += v; q += v * v;
    }
    atomicAdd(&g_bnsum[t], s);
    atomicAdd(&g_bnsum[256 + t], q);
}

__device__ __forceinline__ float elu1(float v) { return v > 0.f ? v : expm1f(v); }

__global__ void __launch_bounds__(512, 1) tc_mlp2pq(
    const float* __restrict__ bng, const float* __restrict__ bnb,
    const float* __restrict__ lng, const float* __restrict__ lnb, float* __restrict__ out_x)
{
    extern __shared__ __align__(16) char sm[];
    uint32_t sb = smem_u32(sm);
    int tid = threadIdx.x, wid = tid >> 5, lane = tid & 31;
    int row0 = blockIdx.x * 128;

    float* red  = (float*)sm;
    float* lngs = (float*)(sm + 2048);
    float* lnbs = (float*)(sm + 2560);
    float* bnst = (float*)(sm + 3072);
    if (tid < 128) { lngs[tid] = lng[tid]; lnbs[tid] = lnb[tid]; }
    if (tid < 256) {
        float s = g_bnsum[tid], s2 = g_bnsum[256 + tid];
        float mu = s * (1.0f / N_NODES);
        float var = s2 * (1.0f / N_NODES) - mu * mu;
        float rstd = rsqrtf(var + 1e-5f);
        float sc = rstd * bng[tid];
        bnst[tid] = sc;
        bnst[256 + tid] = bnb[tid] - mu * sc;
    }

    {
        const float4* bh = (const float4*)g_B2h;
        float4* sh = (float4*)(sm + OFF_BH);
        for (int i = tid; i < 4352; i += 512) sh[i] = bh[i];
    }

    int mrow0 = (wid & 7) * 16, nh = wid >> 3;
    uint32_t aRow = mrow0 + (lane & 7) + ((lane >> 3) & 1) * 8;
    uint32_t aAddrH = sb + OFF_AH + aRow * ASTR + (lane >> 4) * 16;
    uint32_t aAddrL = aAddrH + (OFF_AL - OFF_AH);
    uint32_t bLaneRow = (lane & 7) + ((lane >> 3) & 1) * 8;
    uint32_t bLaneN = ((lane >> 4) & 1) * 16 + nh * 128;

    float c[8][4];
#pragma unroll
    for (int t = 0; t < 8; t++)
#pragma unroll
        for (int q = 0; q < 4; q++) c[t][q] = 0.f;

#pragma unroll
    for (int s = 0; s < 2; s++) {
        __syncthreads();
        for (int i = tid; i < 128 * 64; i += 512) {
            int r = i >> 6, k2 = (i & 63) << 1;
            int row = row0 + r;
            float v0 = 0.f, v1 = 0.f;
            if (row < N_NODES) {
                int kc = s * 128 + k2;
                float2 hv = *(const float2*)&g_h1[(size_t)row * 256 + kc];
                v0 = fmaxf(fmaf(hv.x, bnst[kc],     bnst[256 + kc]),     0.f);
                v1 = fmaxf(fmaf(hv.y, bnst[kc + 1], bnst[256 + kc + 1]), 0.f);
            }
            uint32_t uh, ul;
            split2(v0, v1, uh, ul);
            *(uint32_t*)(sm + OFF_AH + r * ASTR + k2 * 2) = uh;
            *(uint32_t*)(sm + OFF_AL + r * ASTR + k2 * 2) = ul;
        }
        __syncthreads();

#pragma unroll
        for (int kst = 0; kst < 8; kst++) {
            uint32_t ah[4], al[4];
            ldmx4(ah, aAddrH + kst * 32);
            ldmx4(al, aAddrL + kst * 32);
            uint32_t bAddr = sb + OFF_BH + (s * 128 + kst * 16 + bLaneRow) * 272 + bLaneN;
#pragma unroll
            for (int tp = 0; tp < 4; tp++) {
                uint32_t bh[4];
                ldmx4t(bh, bAddr + tp * 32);
                mma16816(c[2 * tp],     ah, bh[0], bh[1]);
                mma16816(c[2 * tp],     al, bh[0], bh[1]);
                mma16816(c[2 * tp + 1], ah, bh[2], bh[3]);
                mma16816(c[2 * tp + 1], al, bh[2], bh[3]);
            }
        }
    }

    __syncthreads();
    {
        const float4* bh = (const float4*)g_B3h;
        float4* sh = (float4*)(sm + OFF_BH);
        for (int i = tid; i < 4224; i += 512) sh[i] = bh[i];
    }

    float s1a = 0.f, s2a = 0.f, s1b = 0.f, s2b = 0.f;
#pragma unroll
    for (int t = 0; t < 8; t++) {
        s1a += c[t][0] + c[t][1];
        s2a += c[t][0] * c[t][0] + c[t][1] * c[t][1];
        s1b += c[t][2] + c[t][3];
        s2b += c[t][2] * c[t][2] + c[t][3] * c[t][3];
    }
#pragma unroll
    for (int o = 1; o < 4; o <<= 1) {
        s1a += __shfl_xor_sync(~0u, s1a, o);
        s2a += __shfl_xor_sync(~0u, s2a, o);
        s1b += __shfl_xor_sync(~0u, s1b, o);
        s2b += __shfl_xor_sync(~0u, s2b, o);
    }
    __syncthreads();
    if ((lane & 3) == 0) {
        int r = mrow0 + (lane >> 2);
        red[r * 4 + nh * 2]           = s1a;
        red[r * 4 + nh * 2 + 1]       = s2a;
        red[(r + 8) * 4 + nh * 2]     = s1b;
        red[(r + 8) * 4 + nh * 2 + 1] = s2b;
    }
    __syncthreads();
    {
        int ra = mrow0 + (lane >> 2), rb = ra + 8;
        float mua = (red[ra * 4] + red[ra * 4 + 2]) * (1.f / 128.f);
        float vara = (red[ra * 4 + 1] + red[ra * 4 + 3]) * (1.f / 128.f) - mua * mua;
        float rsa = rsqrtf(vara + 1e-5f);
        float mub = (red[rb * 4] + red[rb * 4 + 2]) * (1.f / 128.f);
        float varb = (red[rb * 4 + 1] + red[rb * 4 + 3]) * (1.f / 128.f) - mub * mub;
        float rsb = rsqrtf(varb + 1e-5f);
        int rowa = row0 + ra, rowb = row0 + rb;
#pragma unroll
        for (int t = 0; t < 8; t++) {
            int col = nh * 64 + t * 8 + (lane & 3) * 2;
            float oax = elu1((c[t][0] - mua) * rsa * lngs[col]     + lnbs[col]);
            float oay = elu1((c[t][1] - mua) * rsa * lngs[col + 1] + lnbs[col + 1]);
            float obx = elu1((c[t][2] - mub) * rsb * lngs[col]     + lnbs[col]);
            float oby = elu1((c[t][3] - mub) * rsb * lngs[col + 1] + lnbs[col + 1]);
            if (rowa < N_NODES) *(float2*)&out_x[(size_t)rowa * DIM + col] = make_float2(oax, oay);
            if (rowb < N_NODES) *(float2*)&out_x[(size_t)rowb * DIM + col] = make_float2(obx, oby);
            uint32_t uh, ul;
            split2(oax, oay, uh, ul);
            *(uint32_t*)(sm + OFF_AH + ra * ASTR + col * 2) = uh;
            *(uint32_t*)(sm + OFF_AL + ra * ASTR + col * 2) = ul;
            split2(obx, oby, uh, ul);
            *(uint32_t*)(sm + OFF_AH + rb * ASTR + col * 2) = uh;
            *(uint32_t*)(sm + OFF_AL + rb * ASTR + col * 2) = ul;
        }
    }
    __syncthreads();

    uint32_t bLaneN2 = ((lane >> 4) & 1) * 16 + nh * 256;
    float c2[16][4];
#pragma unroll
    for (int t = 0; t < 16; t++)
#pragma unroll
        for (int q = 0; q < 4; q++) c2[t][q] = 0.f;

#pragma unroll
    for (int kst = 0; kst < 8; kst++) {
        uint32_t ah[4], al[4];
        ldmx4(ah, aAddrH + kst * 32);
        ldmx4(al, aAddrL + kst * 32);
        uint32_t bAddr = sb + OFF_BH + (kst * 16 + bLaneRow) * 528 + bLaneN2;
#pragma unroll
        for (int tp = 0; tp < 8; tp++) {
            uint32_t bh[4];
            ldmx4t(bh, bAddr + tp * 32);
            mma16816(c2[2 * tp],     ah, bh[0], bh[1]);
            mma16816(c2[2 * tp],     al, bh[0], bh[1]);
            mma16816(c2[2 * tp + 1], ah, bh[2], bh[3]);
            mma16816(c2[2 * tp + 1], al, bh[2], bh[3]);
        }
    }

    int rbase = row0 + mrow0 + (lane >> 2);
    int cbase = nh * 128 + (lane & 3) * 2;
#pragma unroll
    for (int t = 0; t < 16; t++) {
        int n0 = cbase + t * 8;
        if (rbase < N_NODES)     *(float2*)&g_PQ[(size_t)rbase * 256 + n0]       = make_float2(c2[t][0], c2[t][1]);
        if (rbase + 8 < N_NODES) *(float2*)&g_PQ[(size_t)(rbase + 8) * 256 + n0] = make_float2(c2[t][2], c2[t][3]);
    }
}

__global__ void __launch_bounds__(256) edge_out(
    const float* __restrict__ be, const float* __restrict__ lng, const float* __restrict__ lnb,
    float* __restrict__ out_e)
{
    int gw = (blockIdx.x * 256 + threadIdx.x) >> 5;
    int lane = threadIdx.x & 31;
    if (gw >= N_NODES) return;
    int half = lane >> 4, cl = lane & 15;
    int j0 = cl * 8;

    float4 gv0 = *(const float4*)(lng + j0), gv1 = *(const float4*)(lng + j0 + 4);
    float4 bv0 = *(const float4*)(lnb + j0), bv1 = *(const float4*)(lnb + j0 + 4);
    float4 qb0, qb1;
    {
        float4 be0 = *(const float4*)(be + j0), be1 = *(const float4*)(be + j0 + 4);
        float4 qv0 = *(const float4*)&g_PQ[(size_t)gw * 256 + 128 + j0];
        float4 qv1 = *(const float4*)&g_PQ[(size_t)gw * 256 + 128 + j0 + 4];
        qb0.x = qv0.x + be0.x; qb0.y = qv0.y + be0.y; qb0.z = qv0.z + be0.z; qb0.w = qv0.w + be0.w;
        qb1.x = qv1.x + be1.x; qb1.y = qv1.y + be1.y; qb1.z = qv1.z + be1.z; qb1.w = qv1.w + be1.w;
    }
    int beg = g_off[gw];
    int end = (gw == N_NODES - 1) ? N_EDGES : g_off[gw + 1];

    for (int b = beg; b < end; b += 32) {
        int j = b + lane;
        int sl = 0, el = 0;
        if (j < end) { float4 e4 = g_edge[j]; sl = __float_as_int(e4.x); el = __float_as_int(e4.z); }
        int cnt = min(32, end - b);
        for (int q = 0; q < cnt; q += 2) {
            int idx = q + half;
            int s_e = __shfl_sync(0xffffffffu, sl, idx);
            int e_e = __shfl_sync(0xffffffffu, el, idx);
            bool valid = idx < cnt;
            const float4* pp = (const float4*)&g_PQ[(size_t)s_e * 256 + j0];
            float4 p0 = pp[0], p1 = pp[1];
            float g0 = fgelu(p0.x + qb0.x);
            float g1 = fgelu(p0.y + qb0.y);
            float g2 = fgelu(p0.z + qb0.z);
            float g3 = fgelu(p0.w + qb0.w);
            float g4 = fgelu(p1.x + qb1.x);
            float g5 = fgelu(p1.y + qb1.y);
            float g6 = fgelu(p1.z + qb1.z);
            float g7 = fgelu(p1.w + qb1.w);
            float s1 = g0 + g1 + g2 + g3 + g4 + g5 + g6 + g7;
            float s2 = g0 * g0 + g1 * g1 + g2 * g2 + g3 * g3
                     + g4 * g4 + g5 * g5 + g6 * g6 + g7 * g7;
#pragma unroll
            for (int o = 1; o < 16; o <<= 1) {
                s1 += __shfl_xor_sync(0xffffffffu, s1, o);
                s2 += __shfl_xor_sync(0xffffffffu, s2, o);
            }
            float mu = s1 * (1.f / 128.f);
            float var = s2 * (1.f / 128.f) - mu * mu;
            float rstd = rsqrtf(var + 1e-5f);
            if (valid) {
                float4 o0, o1;
                o0.x = (g0 - mu) * rstd * gv0.x + bv0.x;
                o0.y = (g1 - mu) * rstd * gv0.y + bv0.y;
                o0.z = (g2 - mu) * rstd * gv0.z + bv0.z;
                o0.w = (g3 - mu) * rstd * gv0.w + bv0.w;
                o1.x = (g4 - mu) * rstd * gv1.x + bv1.x;
                o1.y = (g5 - mu) * rstd * gv1.y + bv1.y;
                o1.z = (g6 - mu) * rstd * gv1.z + bv1.z;
                o1.w = (g7 - mu) * rstd * gv1.w + bv1.w;
                float4* op = (float4*)(out_e + (size_t)e_e * DIM + j0);
                op[0] = o0;
                op[1] = o1;
            }
        }
    }
}

extern "C" void kernel_launch(void* const* d_in, const int* in_sizes, int n_in,
                              void* d_out, int out_size)
{
    const float* x      = (const float*)d_in[0];
    const int*   ei     = (const int*)  d_in[1];
    const float* ea     = (const float*)d_in[2];
    const float* W_edge = (const float*)d_in[3];
    const float* tptr   = (const float*)d_in[4];
    const float* W1     = (const float*)d_in[5];
    const float* bng    = (const float*)d_in[6];
    const float* bnb    = (const float*)d_in[7];
    const float* W2     = (const float*)d_in[8];
    const float* lng    = (const float*)d_in[9];
    const float* lnb    = (const float*)d_in[10];
    const float* We     = (const float*)d_in[11];
    const float* be     = (const float*)d_in[12];
    const float* lneg   = (const float*)d_in[13];
    const float* lneb   = (const float*)d_in[14];

    const int* src = ei;
    const int* dst = ei + N_EDGES;

    float* out_x = (float*)d_out;
    float* out_e = out_x + (size_t)N_NODES * DIM;

    void *bnp, *b1h, *ghp, *h1p;
    cudaGetSymbolAddress(&bnp, g_bnsum);
    cudaGetSymbolAddress(&b1h, g_B1h);
    cudaGetSymbolAddress(&ghp, g_h);
    cudaGetSymbolAddress(&h1p, g_h1);

    cudaFuncSetAttribute(tc256, cudaFuncAttributeMaxDynamicSharedMemorySize, SM_TC256);
    cudaFuncSetAttribute(tc_mlp2pq, cudaFuncAttributeMaxDynamicSharedMemorySize, SM_MLP2);

    int eblocks256 = (N_EDGES + 255) / 256;
    int ablocks = (N_NODES * 32 + 255) / 256;
    int tblocks = (N_NODES + 127) / 128;

    prep_all<<<384 + 196, 256>>>(W1, We, W2);
    hist<<<eblocks256, 256>>>(dst);
    scan50k<<<1, 1024>>>();
    scatter<<<eblocks256, 256>>>(src, dst, ea);
    cudaMemsetAsync(bnp, 0, sizeof(float) * 512, 0);
    aggregate<<<ablocks, 256>>>(x, W_edge, tptr);

    tc256<<<tblocks, 512, SM_TC256>>>((const float*)ghp, (const u16*)b1h, (float*)h1p);
    bn_reduce<<<200, 256>>>();
    tc_mlp2pq<<<tblocks, 512, SM_MLP2>>>(bng, bnb, lng, lnb, out_x);
    edge_out<<<ablocks, 256>>>(be, lneg, lneb, out_e);
}

// round 15
// speedup vs baseline: 1.0147x; 1.0147x over previous
#include <cuda_runtime.h>
#include <cuda_fp16.h>
#include <math.h>
#include <stdint.h>

#define N_NODES 50000
#define N_EDGES 800000
#define DIM 128

typedef unsigned long long ull;
typedef unsigned short u16;

__device__ float g_h[(size_t)N_NODES * DIM];
__device__ float g_h1[(size_t)N_NODES * 256];
__device__ float g_PQ[(size_t)N_NODES * 256];
__device__ float4 g_edge[(size_t)N_EDGES];
__device__ int g_cnt[N_NODES];
__device__ int g_off[N_NODES];
__device__ int g_cur[N_NODES];
__device__ float g_bnsum[512];
__device__ __align__(16) u16 g_B1h[128 * 264];
__device__ __align__(16) u16 g_B3h[128 * 264];
__device__ __align__(16) u16 g_B2h[256 * 136];

__device__ __forceinline__ uint32_t smem_u32(const void* p) {
    uint32_t a;
    asm("{ .reg .u64 t; cvta.to.shared.u64 t, %1; cvt.u32.u64 %0, t; }" : "=r"(a) : "l"(p));
    return a;
}
__device__ __forceinline__ void ldmx4(uint32_t* r, uint32_t addr) {
    asm volatile("ldmatrix.sync.aligned.m8n8.x4.shared.b16 {%0,%1,%2,%3}, [%4];"
        : "=r"(r[0]), "=r"(r[1]), "=r"(r[2]), "=r"(r[3]) : "r"(addr));
}
__device__ __forceinline__ void ldmx4t(uint32_t* r, uint32_t addr) {
    asm volatile("ldmatrix.sync.aligned.m8n8.x4.trans.shared.b16 {%0,%1,%2,%3}, [%4];"
        : "=r"(r[0]), "=r"(r[1]), "=r"(r[2]), "=r"(r[3]) : "r"(addr));
}
__device__ __forceinline__ void mma16816(float* c, const uint32_t* a, uint32_t b0, uint32_t b1) {
    asm volatile("mma.sync.aligned.m16n8k16.row.col.f32.f16.f16.f32 "
        "{%0,%1,%2,%3}, {%4,%5,%6,%7}, {%8,%9}, {%0,%1,%2,%3};"
        : "+f"(c[0]), "+f"(c[1]), "+f"(c[2]), "+f"(c[3])
        : "r"(a[0]), "r"(a[1]), "r"(a[2]), "r"(a[3]), "r"(b0), "r"(b1));
}
__device__ __forceinline__ void split2(float a, float b, uint32_t& uh, uint32_t& ul) {
    __half h0 = __float2half_rn(a), h1 = __float2half_rn(b);
    float r0 = a - __half2float(h0), r1 = b - __half2float(h1);
    __half l0 = __float2half_rn(r0), l1 = __float2half_rn(r1);
    uh = (uint32_t)(*(u16*)&h0) | ((uint32_t)(*(u16*)&h1) << 16);
    ul = (uint32_t)(*(u16*)&l0) | ((uint32_t)(*(u16*)&l1) << 16);
}
__device__ __forceinline__ float fgelu(float v) {
    float x = fabsf(v) * 0.70710678118654752f;
    float t = __fdividef(1.0f, fmaf(0.3275911f, x, 1.0f));
    float poly = t * fmaf(t, fmaf(t, fmaf(t, fmaf(t, 1.061405429f, -1.453152027f),
                  1.421413741f), -0.284496736f), 0.254829592f);
    float ex = __expf(-x * x);
    float erf_abs = fmaf(-poly, ex, 1.0f);
    float erf_v = copysignf(erf_abs, v);
    return 0.5f * v * (1.0f + erf_v);
}

#define CTRL 8192
#define ASTR 272
#define OFF_AH CTRL
#define OFF_AL (OFF_AH + 128 * ASTR)
#define OFF_BH (OFF_AL + 128 * ASTR)
#define SM_TC256 (OFF_BH + 67584)
#define SM_MLP2  (OFF_BH + 69632)

__global__ void __launch_bounds__(256) prep_all(
    const float* __restrict__ W1, const float* __restrict__ We, const float* __restrict__ W2)
{
    int b = blockIdx.x;
    if (b >= 384) {
        int i = (b - 384) * 256 + threadIdx.x;
        if (i < N_NODES) g_cnt[i] = 0;
        return;
    }
    int li = (b % 128) * 256 + threadIdx.x;
    if (b < 256) {
        int j = li >> 7, k = li & 127;
        float v = (b < 128) ? W1[j * 128 + k]
                : ((j < 128) ? We[j * 256 + k] : We[(j - 128) * 256 + 128 + k]);
        __half hb = __float2half_rn(v);
        u16* Bh = (b < 128) ? g_B1h : g_B3h;
        Bh[k * 264 + j] = *(u16*)&hb;
    } else {
        int j = li >> 8, k = li & 255;
        __half hb = __float2half_rn(W2[j * 256 + k]);
        g_B2h[k * 136 + j] = *(u16*)&hb;
    }
}

__global__ void __launch_bounds__(256) hist(const int* __restrict__ dst)
{
    int e = blockIdx.x * 256 + threadIdx.x;
    if (e < N_EDGES) atomicAdd(&g_cnt[dst[e]], 1);
}

__global__ void __launch_bounds__(1024) scan50k()
{
    __shared__ int wsum[32];
    __shared__ int sh_carry;
    int tid = threadIdx.x, lane = tid & 31, w = tid >> 5;
    if (tid == 0) sh_carry = 0;
    __syncthreads();
    for (int base = 0; base < N_NODES; base += 1024) {
        int i = base + tid;
        int v = (i < N_NODES) ? g_cnt[i] : 0;
        int x = v;
#pragma unroll
        for (int o = 1; o < 32; o <<= 1) { int y = __shfl_up_sync(~0u, x, o); if (lane >= o) x += y; }
        if (lane == 31) wsum[w] = x;
        __syncthreads();
        if (w == 0) {
            int s = wsum[lane];
#pragma unroll
            for (int o = 1; o < 32; o <<= 1) { int y = __shfl_up_sync(~0u, s, o); if (lane >= o) s += y; }
            wsum[lane] = s;
        }
        __syncthreads();
        int warp_excl = (w == 0) ? 0 : wsum[w - 1];
        int carry = sh_carry;
        int excl = carry + warp_excl + x - v;
        if (i < N_NODES) { g_off[i] = excl; g_cur[i] = excl; }
        __syncthreads();
        if (tid == 1023) sh_carry = carry + wsum[31];
        __syncthreads();
    }
}

__global__ void __launch_bounds__(256) scatter(
    const int* __restrict__ src, const int* __restrict__ dst, const float* __restrict__ ea)
{
    int e = blockIdx.x * 256 + threadIdx.x;
    if (e >= N_EDGES) return;
    int d = dst[e];
    int pos = atomicAdd(&g_cur[d], 1);
    g_edge[pos] = make_float4(__int_as_float(src[e]), ea[e], __int_as_float(e), 0.f);
}

// ---------------- aggregate: warp per node, prefetched gather (R13 form) ----------------
__global__ void __launch_bounds__(256) aggregate(
    const float* __restrict__ x, const float* __restrict__ W_edge, const float* __restrict__ tptr)
{
    int gw = (blockIdx.x * 256 + threadIdx.x) >> 5;
    int lane = threadIdx.x & 31;
    if (gw >= N_NODES) return;
    const float t = tptr[0];
    float4 w4 = *(const float4*)&W_edge[lane * 4];

    int beg = g_off[gw];
    int end = (gw == N_NODES - 1) ? N_EDGES : g_off[gw + 1];

    float4 aE = make_float4(0.f, 0.f, 0.f, 0.f);
    float4 aM = make_float4(0.f, 0.f, 0.f, 0.f);

    for (int b = beg; b < end; b += 32) {
        int j = b + lane;
        float2 ed = make_float2(0.f, 0.f);
        if (j < end) { float4 e4 = g_edge[j]; ed = make_float2(e4.x, e4.y); }
        int cnt = min(32, end - b);
        int s_cur = __shfl_sync(0xffffffffu, __float_as_int(ed.x), 0);
        float a_cur = __shfl_sync(0xffffffffu, ed.y, 0);
        float4 xv = *(const float4*)&x[(size_t)s_cur * DIM + lane * 4];
        for (int q = 0; q < cnt; q++) {
            float4 xv_n = xv;
            float a_n = a_cur;
            if (q + 1 < cnt) {
                int s_n = __shfl_sync(0xffffffffu, __float_as_int(ed.x), q + 1);
                a_n = __shfl_sync(0xffffffffu, ed.y, q + 1);
                xv_n = *(const float4*)&x[(size_t)s_n * DIM + lane * 4];
            }
            float a = a_cur;
            float m0 = fmaxf(fmaf(a, w4.x, xv.x), 0.f) + 1e-7f;
            float m1 = fmaxf(fmaf(a, w4.y, xv.y), 0.f) + 1e-7f;
            float m2 = fmaxf(fmaf(a, w4.z, xv.z), 0.f) + 1e-7f;
            float m3 = fmaxf(fmaf(a, w4.w, xv.w), 0.f) + 1e-7f;
            float e0 = __expf(m0 * t), e1 = __expf(m1 * t);
            float e2 = __expf(m2 * t), e3 = __expf(m3 * t);
            aE.x += e0; aE.y += e1; aE.z += e2; aE.w += e3;
            aM.x = fmaf(m0, e0, aM.x); aM.y = fmaf(m1, e1, aM.y);
            aM.z = fmaf(m2, e2, aM.z); aM.w = fmaf(m3, e3, aM.w);
            xv = xv_n;
            a_cur = a_n;
        }
    }
    float4 xn = *(const float4*)&x[(size_t)gw * DIM + lane * 4];
    float4 h;
    h.x = aM.x / (aE.x + 1e-16f) + xn.x;
    h.y = aM.y / (aE.y + 1e-16f) + xn.y;
    h.z = aM.z / (aE.z + 1e-16f) + xn.z;
    h.w = aM.w / (aE.w + 1e-16f) + xn.w;
    *(float4*)&g_h[(size_t)gw * DIM + lane * 4] = h;
}

__global__ void __launch_bounds__(512, 1) tc256(
    const float* __restrict__ in, const u16* __restrict__ Bh, float* __restrict__ out)
{
    extern __shared__ __align__(16) char sm[];
    uint32_t sb = smem_u32(sm);
    int tid = threadIdx.x, wid = tid >> 5, lane = tid & 31;
    int row0 = blockIdx.x * 128;

    {
        const float4* bh = (const float4*)Bh;
        float4* sh = (float4*)(sm + OFF_BH);
        for (int i = tid; i < 4224; i += 512) sh[i] = bh[i];
    }
    for (int i = tid; i < 128 * 64; i += 512) {
        int r = i >> 6, k2 = (i & 63) << 1;
        int row = row0 + r;
        float2 hv = make_float2(0.f, 0.f);
        if (row < N_NODES) hv = *(const float2*)&in[(size_t)row * 128 + k2];
        uint32_t uh, ul;
        split2(hv.x, hv.y, uh, ul);
        *(uint32_t*)(sm + OFF_AH + r * ASTR + k2 * 2) = uh;
        *(uint32_t*)(sm + OFF_AL + r * ASTR + k2 * 2) = ul;
    }
    __syncthreads();

    int mrow0 = (wid & 7) * 16, nh = wid >> 3;
    uint32_t aRow = mrow0 + (lane & 7) + ((lane >> 3) & 1) * 8;
    uint32_t aAddrH = sb + OFF_AH + aRow * ASTR + (lane >> 4) * 16;
    uint32_t aAddrL = aAddrH + (OFF_AL - OFF_AH);
    uint32_t bLaneRow = (lane & 7) + ((lane >> 3) & 1) * 8;
    uint32_t bLaneN = ((lane >> 4) & 1) * 16 + nh * 256;

    float c[16][4];
#pragma unroll
    for (int t = 0; t < 16; t++)
#pragma unroll
        for (int q = 0; q < 4; q++) c[t][q] = 0.f;

#pragma unroll
    for (int kst = 0; kst < 8; kst++) {
        uint32_t ah[4], al[4];
        ldmx4(ah, aAddrH + kst * 32);
        ldmx4(al, aAddrL + kst * 32);
        uint32_t bAddr = sb + OFF_BH + (kst * 16 + bLaneRow) * 528 + bLaneN;
#pragma unroll
        for (int tp = 0; tp < 8; tp++) {
            uint32_t bh[4];
            ldmx4t(bh, bAddr + tp * 32);
            mma16816(c[2 * tp],     ah, bh[0], bh[1]);
            mma16816(c[2 * tp],     al, bh[0], bh[1]);
            mma16816(c[2 * tp + 1], ah, bh[2], bh[3]);
            mma16816(c[2 * tp + 1], al, bh[2], bh[3]);
        }
    }

    int rbase = row0 + mrow0 + (lane >> 2);
    int cbase = nh * 128 + (lane & 3) * 2;
#pragma unroll
    for (int t = 0; t < 16; t++) {
        int n0 = cbase + t * 8;
        if (rbase < N_NODES)     *(float2*)&out[(size_t)rbase * 256 + n0]       = make_float2(c[t][0], c[t][1]);
        if (rbase + 8 < N_NODES) *(float2*)&out[(size_t)(rbase + 8) * 256 + n0] = make_float2(c[t][2], c[t][3]);
    }
}

__global__ void __launch_bounds__(256) bn_reduce()
{
    int t = threadIdx.x;
    int r0 = blockIdx.x * 250, r1 = min(r0 + 250, N_NODES);
    float s = 0.f, q = 0.f;
    for (int row = r0; row < r1; row++) {
        float v = g_h1[(size_t)row * 256 + t];
        s += v; q += v * v;
    }
    atomicAdd(&g_bnsum[t], s);
    atomicAdd(&g_bnsum[256 + t], q);
}

__device__ __forceinline__ float elu1(float v) { return v > 0.f ? v : expm1f(v); }

__global__ void __launch_bounds__(512, 1) tc_mlp2pq(
    const float* __restrict__ bng, const float* __restrict__ bnb,
    const float* __restrict__ lng, const float* __restrict__ lnb, float* __restrict__ out_x)
{
    extern __shared__ __align__(16) char sm[];
    uint32_t sb = smem_u32(sm);
    int tid = threadIdx.x, wid = tid >> 5, lane = tid & 31;
    int row0 = blockIdx.x * 128;

    float* red  = (float*)sm;
    float* lngs = (float*)(sm + 2048);
    float* lnbs = (float*)(sm + 2560);
    float* bnst = (float*)(sm + 3072);
    if (tid < 128) { lngs[tid] = lng[tid]; lnbs[tid] = lnb[tid]; }
    if (tid < 256) {
        float s = g_bnsum[tid], s2 = g_bnsum[256 + tid];
        float mu = s * (1.0f / N_NODES);
        float var = s2 * (1.0f / N_NODES) - mu * mu;
        float rstd = rsqrtf(var + 1e-5f);
        float sc = rstd * bng[tid];
        bnst[tid] = sc;
        bnst[256 + tid] = bnb[tid] - mu * sc;
    }

    {
        const float4* bh = (const float4*)g_B2h;
        float4* sh = (float4*)(sm + OFF_BH);
        for (int i = tid; i < 4352; i += 512) sh[i] = bh[i];
    }

    int mrow0 = (wid & 7) * 16, nh = wid >> 3;
    uint32_t aRow = mrow0 + (lane & 7) + ((lane >> 3) & 1) * 8;
    uint32_t aAddrH = sb + OFF_AH + aRow * ASTR + (lane >> 4) * 16;
    uint32_t aAddrL = aAddrH + (OFF_AL - OFF_AH);
    uint32_t bLaneRow = (lane & 7) + ((lane >> 3) & 1) * 8;
    uint32_t bLaneN = ((lane >> 4) & 1) * 16 + nh * 128;

    float c[8][4];
#pragma unroll
    for (int t = 0; t < 8; t++)
#pragma unroll
        for (int q = 0; q < 4; q++) c[t][q] = 0.f;

#pragma unroll
    for (int s = 0; s < 2; s++) {
        __syncthreads();
        for (int i = tid; i < 128 * 64; i += 512) {
            int r = i >> 6, k2 = (i & 63) << 1;
            int row = row0 + r;
            float v0 = 0.f, v1 = 0.f;
            if (row < N_NODES) {
                int kc = s * 128 + k2;
                float2 hv = *(const float2*)&g_h1[(size_t)row * 256 + kc];
                v0 = fmaxf(fmaf(hv.x, bnst[kc],     bnst[256 + kc]),     0.f);
                v1 = fmaxf(fmaf(hv.y, bnst[kc + 1], bnst[256 + kc + 1]), 0.f);
            }
            uint32_t uh, ul;
            split2(v0, v1, uh, ul);
            *(uint32_t*)(sm + OFF_AH + r * ASTR + k2 * 2) = uh;
            *(uint32_t*)(sm + OFF_AL + r * ASTR + k2 * 2) = ul;
        }
        __syncthreads();

#pragma unroll
        for (int kst = 0; kst < 8; kst++) {
            uint32_t ah[4], al[4];
            ldmx4(ah, aAddrH + kst * 32);
            ldmx4(al, aAddrL + kst * 32);
            uint32_t bAddr = sb + OFF_BH + (s * 128 + kst * 16 + bLaneRow) * 272 + bLaneN;
#pragma unroll
            for (int tp = 0; tp < 4; tp++) {
                uint32_t bh[4];
                ldmx4t(bh, bAddr + tp * 32);
                mma16816(c[2 * tp],     ah, bh[0], bh[1]);
                mma16816(c[2 * tp],     al, bh[0], bh[1]);
                mma16816(c[2 * tp + 1], ah, bh[2], bh[3]);
                mma16816(c[2 * tp + 1], al, bh[2], bh[3]);
            }
        }
    }

    __syncthreads();
    {
        const float4* bh = (const float4*)g_B3h;
        float4* sh = (float4*)(sm + OFF_BH);
        for (int i = tid; i < 4224; i += 512) sh[i] = bh[i];
    }

    float s1a = 0.f, s2a = 0.f, s1b = 0.f, s2b = 0.f;
#pragma unroll
    for (int t = 0; t < 8; t++) {
        s1a += c[t][0] + c[t][1];
        s2a += c[t][0] * c[t][0] + c[t][1] * c[t][1];
        s1b += c[t][2] + c[t][3];
        s2b += c[t][2] * c[t][2] + c[t][3] * c[t][3];
    }
#pragma unroll
    for (int o = 1; o < 4; o <<= 1) {
        s1a += __shfl_xor_sync(~0u, s1a, o);
        s2a += __shfl_xor_sync(~0u, s2a, o);
        s1b += __shfl_xor_sync(~0u, s1b, o);
        s2b += __shfl_xor_sync(~0u, s2b, o);
    }
    __syncthreads();
    if ((lane & 3) == 0) {
        int r = mrow0 + (lane >> 2);
        red[r * 4 + nh * 2]           = s1a;
        red[r * 4 + nh * 2 + 1]       = s2a;
        red[(r + 8) * 4 + nh * 2]     = s1b;
        red[(r + 8) * 4 + nh * 2 + 1] = s2b;
    }
    __syncthreads();
    {
        int ra = mrow0 + (lane >> 2), rb = ra + 8;
        float mua = (red[ra * 4] + red[ra * 4 + 2]) * (1.f / 128.f);
        float vara = (red[ra * 4 + 1] + red[ra * 4 + 3]) * (1.f / 128.f) - mua * mua;
        float rsa = rsqrtf(vara + 1e-5f);
        float mub = (red[rb * 4] + red[rb * 4 + 2]) * (1.f / 128.f);
        float varb = (red[rb * 4 + 1] + red[rb * 4 + 3]) * (1.f / 128.f) - mub * mub;
        float rsb = rsqrtf(varb + 1e-5f);
        int rowa = row0 + ra, rowb = row0 + rb;
#pragma unroll
        for (int t = 0; t < 8; t++) {
            int col = nh * 64 + t * 8 + (lane & 3) * 2;
            float oax = elu1((c[t][0] - mua) * rsa * lngs[col]     + lnbs[col]);
            float oay = elu1((c[t][1] - mua) * rsa * lngs[col + 1] + lnbs[col + 1]);
            float obx = elu1((c[t][2] - mub) * rsb * lngs[col]     + lnbs[col]);
            float oby = elu1((c[t][3] - mub) * rsb * lngs[col + 1] + lnbs[col + 1]);
            if (rowa < N_NODES) *(float2*)&out_x[(size_t)rowa * DIM + col] = make_float2(oax, oay);
            if (rowb < N_NODES) *(float2*)&out_x[(size_t)rowb * DIM + col] = make_float2(obx, oby);
            uint32_t uh, ul;
            split2(oax, oay, uh, ul);
            *(uint32_t*)(sm + OFF_AH + ra * ASTR + col * 2) = uh;
            *(uint32_t*)(sm + OFF_AL + ra * ASTR + col * 2) = ul;
            split2(obx, oby, uh, ul);
            *(uint32_t*)(sm + OFF_AH + rb * ASTR + col * 2) = uh;
            *(uint32_t*)(sm + OFF_AL + rb * ASTR + col * 2) = ul;
        }
    }
    __syncthreads();

    uint32_t bLaneN2 = ((lane >> 4) & 1) * 16 + nh * 256;
    float c2[16][4];
#pragma unroll
    for (int t = 0; t < 16; t++)
#pragma unroll
        for (int q = 0; q < 4; q++) c2[t][q] = 0.f;

#pragma unroll
    for (int kst = 0; kst < 8; kst++) {
        uint32_t ah[4], al[4];
        ldmx4(ah, aAddrH + kst * 32);
        ldmx4(al, aAddrL + kst * 32);
        uint32_t bAddr = sb + OFF_BH + (kst * 16 + bLaneRow) * 528 + bLaneN2;
#pragma unroll
        for (int tp = 0; tp < 8; tp++) {
            uint32_t bh[4];
            ldmx4t(bh, bAddr + tp * 32);
            mma16816(c2[2 * tp],     ah, bh[0], bh[1]);
            mma16816(c2[2 * tp],     al, bh[0], bh[1]);
            mma16816(c2[2 * tp + 1], ah, bh[2], bh[3]);
            mma16816(c2[2 * tp + 1], al, bh[2], bh[3]);
        }
    }

    int rbase = row0 + mrow0 + (lane >> 2);
    int cbase = nh * 128 + (lane & 3) * 2;
#pragma unroll
    for (int t = 0; t < 16; t++) {
        int n0 = cbase + t * 8;
        if (rbase < N_NODES)     *(float2*)&g_PQ[(size_t)rbase * 256 + n0]       = make_float2(c2[t][0], c2[t][1]);
        if (rbase + 8 < N_NODES) *(float2*)&g_PQ[(size_t)(rbase + 8) * 256 + n0] = make_float2(c2[t][2], c2[t][3]);
    }
}

__global__ void __launch_bounds__(256) edge_out(
    const float* __restrict__ be, const float* __restrict__ lng, const float* __restrict__ lnb,
    float* __restrict__ out_e)
{
    int gw = (blockIdx.x * 256 + threadIdx.x) >> 5;
    int lane = threadIdx.x & 31;
    if (gw >= N_NODES) return;
    int half = lane >> 4, cl = lane & 15;
    int j0 = cl * 8;

    float4 gv0 = *(const float4*)(lng + j0), gv1 = *(const float4*)(lng + j0 + 4);
    float4 bv0 = *(const float4*)(lnb + j0), bv1 = *(const float4*)(lnb + j0 + 4);
    float4 qb0, qb1;
    {
        float4 be0 = *(const float4*)(be + j0), be1 = *(const float4*)(be + j0 + 4);
        float4 qv0 = *(const float4*)&g_PQ[(size_t)gw * 256 + 128 + j0];
        float4 qv1 = *(const float4*)&g_PQ[(size_t)gw * 256 + 128 + j0 + 4];
        qb0.x = qv0.x + be0.x; qb0.y = qv0.y + be0.y; qb0.z = qv0.z + be0.z; qb0.w = qv0.w + be0.w;
        qb1.x = qv1.x + be1.x; qb1.y = qv1.y + be1.y; qb1.z = qv1.z + be1.z; qb1.w = qv1.w + be1.w;
    }
    int beg = g_off[gw];
    int end = (gw == N_NODES - 1) ? N_EDGES : g_off[gw + 1];

    for (int b = beg; b < end; b += 32) {
        int j = b + lane;
        int sl = 0, el = 0;
        if (j < end) { float4 e4 = g_edge[j]; sl = __float_as_int(e4.x); el = __float_as_int(e4.z); }
        int cnt = min(32, end - b);
        for (int q = 0; q < cnt; q += 2) {
            int idx = q + half;
            int s_e = __shfl_sync(0xffffffffu, sl, idx);
            int e_e = __shfl_sync(0xffffffffu, el, idx);
            bool valid = idx < cnt;
            const float4* pp = (const float4*)&g_PQ[(size_t)s_e * 256 + j0];
            float4 p0 = pp[0], p1 = pp[1];
            float g0 = fgelu(p0.x + qb0.x);
            float g1 = fgelu(p0.y + qb0.y);
            float g2 = fgelu(p0.z + qb0.z);
            float g3 = fgelu(p0.w + qb0.w);
            float g4 = fgelu(p1.x + qb1.x);
            float g5 = fgelu(p1.y + qb1.y);
            float g6 = fgelu(p1.z + qb1.z);
            float g7 = fgelu(p1.w + qb1.w);
            float s1 = g0 + g1 + g2 + g3 + g4 + g5 + g6 + g7;
            float s2 = g0 * g0 + g1 * g1 + g2 * g2 + g3 * g3
                     + g4 * g4 + g5 * g5 + g6 * g6 + g7 * g7;
#pragma unroll
            for (int o = 1; o < 16; o <<= 1) {
                s1 += __shfl_xor_sync(0xffffffffu, s1, o);
                s2 += __shfl_xor_sync(0xffffffffu, s2, o);
            }
            float mu = s1 * (1.f / 128.f);
            float var = s2 * (1.f / 128.f) - mu * mu;
            float rstd = rsqrtf(var + 1e-5f);
            if (valid) {
                float4 o0, o1;
                o0.x = (g0 - mu) * rstd * gv0.x + bv0.x;
                o0.y = (g1 - mu) * rstd * gv0.y + bv0.y;
                o0.z = (g2 - mu) * rstd * gv0.z + bv0.z;
                o0.w = (g3 - mu) * rstd * gv0.w + bv0.w;
                o1.x = (g4 - mu) * rstd * gv1.x + bv1.x;
                o1.y = (g5 - mu) * rstd * gv1.y + bv1.y;
                o1.z = (g6 - mu) * rstd * gv1.z + bv1.z;
                o1.w = (g7 - mu) * rstd * gv1.w + bv1.w;
                float4* op = (float4*)(out_e + (size_t)e_e * DIM + j0);
                op[0] = o0;
                op[1] = o1;
            }
        }
    }
}

extern "C" void kernel_launch(void* const* d_in, const int* in_sizes, int n_in,
                              void* d_out, int out_size)
{
    const float* x      = (const float*)d_in[0];
    const int*   ei     = (const int*)  d_in[1];
    const float* ea     = (const float*)d_in[2];
    const float* W_edge = (const float*)d_in[3];
    const float* tptr   = (const float*)d_in[4];
    const float* W1     = (const float*)d_in[5];
    const float* bng    = (const float*)d_in[6];
    const float* bnb    = (const float*)d_in[7];
    const float* W2     = (const float*)d_in[8];
    const float* lng    = (const float*)d_in[9];
    const float* lnb    = (const float*)d_in[10];
    const float* We     = (const float*)d_in[11];
    const float* be     = (const float*)d_in[12];
    const float* lneg   = (const float*)d_in[13];
    const float* lneb   = (const float*)d_in[14];

    const int* src = ei;
    const int* dst = ei + N_EDGES;

    float* out_x = (float*)d_out;
    float* out_e = out_x + (size_t)N_NODES * DIM;

    void *bnp, *b1h, *ghp, *h1p;
    cudaGetSymbolAddress(&bnp, g_bnsum);
    cudaGetSymbolAddress(&b1h, g_B1h);
    cudaGetSymbolAddress(&ghp, g_h);
    cudaGetSymbolAddress(&h1p, g_h1);

    cudaFuncSetAttribute(tc256, cudaFuncAttributeMaxDynamicSharedMemorySize, SM_TC256);
    cudaFuncSetAttribute(tc_mlp2pq, cudaFuncAttributeMaxDynamicSharedMemorySize, SM_MLP2);

    int eblocks256 = (N_EDGES + 255) / 256;
    int ablocks = (N_NODES * 32 + 255) / 256;
    int tblocks = (N_NODES + 127) / 128;

    prep_all<<<384 + 196, 256>>>(W1, We, W2);
    hist<<<eblocks256, 256>>>(dst);
    scan50k<<<1, 1024>>>();
    scatter<<<eblocks256, 256>>>(src, dst, ea);
    cudaMemsetAsync(bnp, 0, sizeof(float) * 512, 0);
    aggregate<<<ablocks, 256>>>(x, W_edge, tptr);

    tc256<<<tblocks, 512, SM_TC256>>>((const float*)ghp, (const u16*)b1h, (float*)h1p);
    bn_reduce<<<200, 256>>>();
    tc_mlp2pq<<<tblocks, 512, SM_MLP2>>>(bng, bnb, lng, lnb, out_x);
    edge_out<<<ablocks, 256>>>(be, lneg, lneb, out_e);
}

// round 16
// speedup vs baseline: 1.0212x; 1.0064x over previous
#include <cuda_runtime.h>
#include <cuda_fp16.h>
#include <math.h>
#include <stdint.h>

#define N_NODES 50000
#define N_EDGES 800000
#define DIM 128

typedef unsigned long long ull;
typedef unsigned short u16;

__device__ float g_h[(size_t)N_NODES * DIM];
__device__ float g_h1[(size_t)N_NODES * 256];
__device__ __align__(16) u16 g_PQh[(size_t)N_NODES * 256];   // fp16 [P|Q]
__device__ float2 g_edgeA[(size_t)N_EDGES];                  // sorted (src_asf, ea)
__device__ int2  g_edgeE[(size_t)N_EDGES];                   // sorted (src, eid)
__device__ int g_cnt[N_NODES];
__device__ int g_off[N_NODES];
__device__ int g_cur[N_NODES];
__device__ float g_bnsum[512];
__device__ __align__(16) u16 g_B1h[128 * 264];
__device__ __align__(16) u16 g_B3h[128 * 264];
__device__ __align__(16) u16 g_B2h[256 * 136];

__device__ __forceinline__ uint32_t smem_u32(const void* p) {
    uint32_t a;
    asm("{ .reg .u64 t; cvta.to.shared.u64 t, %1; cvt.u32.u64 %0, t; }" : "=r"(a) : "l"(p));
    return a;
}
__device__ __forceinline__ void ldmx4(uint32_t* r, uint32_t addr) {
    asm volatile("ldmatrix.sync.aligned.m8n8.x4.shared.b16 {%0,%1,%2,%3}, [%4];"
        : "=r"(r[0]), "=r"(r[1]), "=r"(r[2]), "=r"(r[3]) : "r"(addr));
}
__device__ __forceinline__ void ldmx4t(uint32_t* r, uint32_t addr) {
    asm volatile("ldmatrix.sync.aligned.m8n8.x4.trans.shared.b16 {%0,%1,%2,%3}, [%4];"
        : "=r"(r[0]), "=r"(r[1]), "=r"(r[2]), "=r"(r[3]) : "r"(addr));
}
__device__ __forceinline__ void mma16816(float* c, const uint32_t* a, uint32_t b0, uint32_t b1) {
    asm volatile("mma.sync.aligned.m16n8k16.row.col.f32.f16.f16.f32 "
        "{%0,%1,%2,%3}, {%4,%5,%6,%7}, {%8,%9}, {%0,%1,%2,%3};"
        : "+f"(c[0]), "+f"(c[1]), "+f"(c[2]), "+f"(c[3])
        : "r"(a[0]), "r"(a[1]), "r"(a[2]), "r"(a[3]), "r"(b0), "r"(b1));
}
__device__ __forceinline__ void split2(float a, float b, uint32_t& uh, uint32_t& ul) {
    __half h0 = __float2half_rn(a), h1 = __float2half_rn(b);
    float r0 = a - __half2float(h0), r1 = b - __half2float(h1);
    __half l0 = __float2half_rn(r0), l1 = __float2half_rn(r1);
    uh = (uint32_t)(*(u16*)&h0) | ((uint32_t)(*(u16*)&h1) << 16);
    ul = (uint32_t)(*(u16*)&l0) | ((uint32_t)(*(u16*)&l1) << 16);
}
__device__ __forceinline__ float fgelu(float v) {
    float x = fabsf(v) * 0.70710678118654752f;
    float t = __fdividef(1.0f, fmaf(0.3275911f, x, 1.0f));
    float poly = t * fmaf(t, fmaf(t, fmaf(t, fmaf(t, 1.061405429f, -1.453152027f),
                  1.421413741f), -0.284496736f), 0.254829592f);
    float ex = __expf(-x * x);
    float erf_abs = fmaf(-poly, ex, 1.0f);
    float erf_v = copysignf(erf_abs, v);
    return 0.5f * v * (1.0f + erf_v);
}

#define CTRL 8192
#define ASTR 272
#define OFF_AH CTRL
#define OFF_AL (OFF_AH + 128 * ASTR)
#define OFF_BH (OFF_AL + 128 * ASTR)
#define SM_TC256 (OFF_BH + 67584)
#define SM_MLP2  (OFF_BH + 69632)

__global__ void __launch_bounds__(256) prep_all(
    const float* __restrict__ W1, const float* __restrict__ We, const float* __restrict__ W2)
{
    int b = blockIdx.x;
    if (b >= 384) {
        int i = (b - 384) * 256 + threadIdx.x;
        if (i < N_NODES) g_cnt[i] = 0;
        return;
    }
    int li = (b % 128) * 256 + threadIdx.x;
    if (b < 256) {
        int j = li >> 7, k = li & 127;
        float v = (b < 128) ? W1[j * 128 + k]
                : ((j < 128) ? We[j * 256 + k] : We[(j - 128) * 256 + 128 + k]);
        __half hb = __float2half_rn(v);
        u16* Bh = (b < 128) ? g_B1h : g_B3h;
        Bh[k * 264 + j] = *(u16*)&hb;
    } else {
        int j = li >> 8, k = li & 255;
        __half hb = __float2half_rn(W2[j * 256 + k]);
        g_B2h[k * 136 + j] = *(u16*)&hb;
    }
}

__global__ void __launch_bounds__(256) hist(const int* __restrict__ dst)
{
    int e = blockIdx.x * 256 + threadIdx.x;
    if (e < N_EDGES) atomicAdd(&g_cnt[dst[e]], 1);
}

__global__ void __launch_bounds__(1024) scan50k()
{
    __shared__ int wsum[32];
    __shared__ int sh_carry;
    int tid = threadIdx.x, lane = tid & 31, w = tid >> 5;
    if (tid == 0) sh_carry = 0;
    __syncthreads();
    for (int base = 0; base < N_NODES; base += 1024) {
        int i = base + tid;
        int v = (i < N_NODES) ? g_cnt[i] : 0;
        int x = v;
#pragma unroll
        for (int o = 1; o < 32; o <<= 1) { int y = __shfl_up_sync(~0u, x, o); if (lane >= o) x += y; }
        if (lane == 31) wsum[w] = x;
        __syncthreads();
        if (w == 0) {
            int s = wsum[lane];
#pragma unroll
            for (int o = 1; o < 32; o <<= 1) { int y = __shfl_up_sync(~0u, s, o); if (lane >= o) s += y; }
            wsum[lane] = s;
        }
        __syncthreads();
        int warp_excl = (w == 0) ? 0 : wsum[w - 1];
        int carry = sh_carry;
        int excl = carry + warp_excl + x - v;
        if (i < N_NODES) { g_off[i] = excl; g_cur[i] = excl; }
        __syncthreads();
        if (tid == 1023) sh_carry = carry + wsum[31];
        __syncthreads();
    }
}

__global__ void __launch_bounds__(256) scatter(
    const int* __restrict__ src, const int* __restrict__ dst, const float* __restrict__ ea)
{
    int e = blockIdx.x * 256 + threadIdx.x;
    if (e >= N_EDGES) return;
    int d = dst[e];
    int s = src[e];
    int pos = atomicAdd(&g_cur[d], 1);
    g_edgeA[pos] = make_float2(__int_as_float(s), ea[e]);
    g_edgeE[pos] = make_int2(s, e);
}

// ---------------- aggregate: warp per node, prefetched gather ----------------
__global__ void __launch_bounds__(256) aggregate(
    const float* __restrict__ x, const float* __restrict__ W_edge, const float* __restrict__ tptr)
{
    int gw = (blockIdx.x * 256 + threadIdx.x) >> 5;
    int lane = threadIdx.x & 31;
    if (gw >= N_NODES) return;
    const float t = tptr[0];
    float4 w4 = *(const float4*)&W_edge[lane * 4];

    int beg = g_off[gw];
    int end = (gw == N_NODES - 1) ? N_EDGES : g_off[gw + 1];

    float4 aE = make_float4(0.f, 0.f, 0.f, 0.f);
    float4 aM = make_float4(0.f, 0.f, 0.f, 0.f);

    for (int b = beg; b < end; b += 32) {
        int j = b + lane;
        float2 ed = make_float2(0.f, 0.f);
        if (j < end) ed = g_edgeA[j];
        int cnt = min(32, end - b);
        int s_cur = __shfl_sync(0xffffffffu, __float_as_int(ed.x), 0);
        float a_cur = __shfl_sync(0xffffffffu, ed.y, 0);
        float4 xv = *(const float4*)&x[(size_t)s_cur * DIM + lane * 4];
        for (int q = 0; q < cnt; q++) {
            float4 xv_n = xv;
            float a_n = a_cur;
            if (q + 1 < cnt) {
                int s_n = __shfl_sync(0xffffffffu, __float_as_int(ed.x), q + 1);
                a_n = __shfl_sync(0xffffffffu, ed.y, q + 1);
                xv_n = *(const float4*)&x[(size_t)s_n * DIM + lane * 4];
            }
            float a = a_cur;
            float m0 = fmaxf(fmaf(a, w4.x, xv.x), 0.f) + 1e-7f;
            float m1 = fmaxf(fmaf(a, w4.y, xv.y), 0.f) + 1e-7f;
            float m2 = fmaxf(fmaf(a, w4.z, xv.z), 0.f) + 1e-7f;
            float m3 = fmaxf(fmaf(a, w4.w, xv.w), 0.f) + 1e-7f;
            float e0 = __expf(m0 * t), e1 = __expf(m1 * t);
            float e2 = __expf(m2 * t), e3 = __expf(m3 * t);
            aE.x += e0; aE.y += e1; aE.z += e2; aE.w += e3;
            aM.x = fmaf(m0, e0, aM.x); aM.y = fmaf(m1, e1, aM.y);
            aM.z = fmaf(m2, e2, aM.z); aM.w = fmaf(m3, e3, aM.w);
            xv = xv_n;
            a_cur = a_n;
        }
    }
    float4 xn = *(const float4*)&x[(size_t)gw * DIM + lane * 4];
    float4 h;
    h.x = aM.x / (aE.x + 1e-16f) + xn.x;
    h.y = aM.y / (aE.y + 1e-16f) + xn.y;
    h.z = aM.z / (aE.z + 1e-16f) + xn.z;
    h.w = aM.w / (aE.w + 1e-16f) + xn.w;
    *(float4*)&g_h[(size_t)gw * DIM + lane * 4] = h;
}

__global__ void __launch_bounds__(512, 1) tc256(
    const float* __restrict__ in, const u16* __restrict__ Bh, float* __restrict__ out)
{
    extern __shared__ __align__(16) char sm[];
    uint32_t sb = smem_u32(sm);
    int tid = threadIdx.x, wid = tid >> 5, lane = tid & 31;
    int row0 = blockIdx.x * 128;

    {
        const float4* bh = (const float4*)Bh;
        float4* sh = (float4*)(sm + OFF_BH);
        for (int i = tid; i < 4224; i += 512) sh[i] = bh[i];
    }
    for (int i = tid; i < 128 * 64; i += 512) {
        int r = i >> 6, k2 = (i & 63) << 1;
        int row = row0 + r;
        float2 hv = make_float2(0.f, 0.f);
        if (row < N_NODES) hv = *(const float2*)&in[(size_t)row * 128 + k2];
        uint32_t uh, ul;
        split2(hv.x, hv.y, uh, ul);
        *(uint32_t*)(sm + OFF_AH + r * ASTR + k2 * 2) = uh;
        *(uint32_t*)(sm + OFF_AL + r * ASTR + k2 * 2) = ul;
    }
    __syncthreads();

    int mrow0 = (wid & 7) * 16, nh = wid >> 3;
    uint32_t aRow = mrow0 + (lane & 7) + ((lane >> 3) & 1) * 8;
    uint32_t aAddrH = sb + OFF_AH + aRow * ASTR + (lane >> 4) * 16;
    uint32_t aAddrL = aAddrH + (OFF_AL - OFF_AH);
    uint32_t bLaneRow = (lane & 7) + ((lane >> 3) & 1) * 8;
    uint32_t bLaneN = ((lane >> 4) & 1) * 16 + nh * 256;

    float c[16][4];
#pragma unroll
    for (int t = 0; t < 16; t++)
#pragma unroll
        for (int q = 0; q < 4; q++) c[t][q] = 0.f;

#pragma unroll
    for (int kst = 0; kst < 8; kst++) {
        uint32_t ah[4], al[4];
        ldmx4(ah, aAddrH + kst * 32);
        ldmx4(al, aAddrL + kst * 32);
        uint32_t bAddr = sb + OFF_BH + (kst * 16 + bLaneRow) * 528 + bLaneN;
#pragma unroll
        for (int tp = 0; tp < 8; tp++) {
            uint32_t bh[4];
            ldmx4t(bh, bAddr + tp * 32);
            mma16816(c[2 * tp],     ah, bh[0], bh[1]);
            mma16816(c[2 * tp],     al, bh[0], bh[1]);
            mma16816(c[2 * tp + 1], ah, bh[2], bh[3]);
            mma16816(c[2 * tp + 1], al, bh[2], bh[3]);
        }
    }

    int rbase = row0 + mrow0 + (lane >> 2);
    int cbase = nh * 128 + (lane & 3) * 2;
#pragma unroll
    for (int t = 0; t < 16; t++) {
        int n0 = cbase + t * 8;
        if (rbase < N_NODES)     *(float2*)&out[(size_t)rbase * 256 + n0]       = make_float2(c[t][0], c[t][1]);
        if (rbase + 8 < N_NODES) *(float2*)&out[(size_t)(rbase + 8) * 256 + n0] = make_float2(c[t][2], c[t][3]);
    }
}

__global__ void __launch_bounds__(256) bn_reduce()
{
    int t = threadIdx.x;
    int r0 = blockIdx.x * 250, r1 = min(r0 + 250, N_NODES);
    float s = 0.f, q = 0.f;
    for (int row = r0; row < r1; row++) {
        float v = g_h1[(size_t)row * 256 + t];
        s += v; q += v * v;
    }
    atomicAdd(&g_bnsum[t], s);
    atomicAdd(&g_bnsum[256 + t], q);
}

__device__ __forceinline__ float elu1(float v) { return v > 0.f ? v : expm1f(v); }

__global__ void __launch_bounds__(512, 1) tc_mlp2pq(
    const float* __restrict__ bng, const float* __restrict__ bnb,
    const float* __restrict__ lng, const float* __restrict__ lnb, float* __restrict__ out_x)
{
    extern __shared__ __align__(16) char sm[];
    uint32_t sb = smem_u32(sm);
    int tid = threadIdx.x, wid = tid >> 5, lane = tid & 31;
    int row0 = blockIdx.x * 128;

    float* red  = (float*)sm;
    float* lngs = (float*)(sm + 2048);
    float* lnbs = (float*)(sm + 2560);
    float* bnst = (float*)(sm + 3072);
    if (tid < 128) { lngs[tid] = lng[tid]; lnbs[tid] = lnb[tid]; }
    if (tid < 256) {
        float s = g_bnsum[tid], s2 = g_bnsum[256 + tid];
        float mu = s * (1.0f / N_NODES);
        float var = s2 * (1.0f / N_NODES) - mu * mu;
        float rstd = rsqrtf(var + 1e-5f);
        float sc = rstd * bng[tid];
        bnst[tid] = sc;
        bnst[256 + tid] = bnb[tid] - mu * sc;
    }

    {
        const float4* bh = (const float4*)g_B2h;
        float4* sh = (float4*)(sm + OFF_BH);
        for (int i = tid; i < 4352; i += 512) sh[i] = bh[i];
    }

    int mrow0 = (wid & 7) * 16, nh = wid >> 3;
    uint32_t aRow = mrow0 + (lane & 7) + ((lane >> 3) & 1) * 8;
    uint32_t aAddrH = sb + OFF_AH + aRow * ASTR + (lane >> 4) * 16;
    uint32_t aAddrL = aAddrH + (OFF_AL - OFF_AH);
    uint32_t bLaneRow = (lane & 7) + ((lane >> 3) & 1) * 8;
    uint32_t bLaneN = ((lane >> 4) & 1) * 16 + nh * 128;

    float c[8][4];
#pragma unroll
    for (int t = 0; t < 8; t++)
#pragma unroll
        for (int q = 0; q < 4; q++) c[t][q] = 0.f;

#pragma unroll
    for (int s = 0; s < 2; s++) {
        __syncthreads();
        for (int i = tid; i < 128 * 64; i += 512) {
            int r = i >> 6, k2 = (i & 63) << 1;
            int row = row0 + r;
            float v0 = 0.f, v1 = 0.f;
            if (row < N_NODES) {
                int kc = s * 128 + k2;
                float2 hv = *(const float2*)&g_h1[(size_t)row * 256 + kc];
                v0 = fmaxf(fmaf(hv.x, bnst[kc],     bnst[256 + kc]),     0.f);
                v1 = fmaxf(fmaf(hv.y, bnst[kc + 1], bnst[256 + kc + 1]), 0.f);
            }
            uint32_t uh, ul;
            split2(v0, v1, uh, ul);
            *(uint32_t*)(sm + OFF_AH + r * ASTR + k2 * 2) = uh;
            *(uint32_t*)(sm + OFF_AL + r * ASTR + k2 * 2) = ul;
        }
        __syncthreads();

#pragma unroll
        for (int kst = 0; kst < 8; kst++) {
            uint32_t ah[4], al[4];
            ldmx4(ah, aAddrH + kst * 32);
            ldmx4(al, aAddrL + kst * 32);
            uint32_t bAddr = sb + OFF_BH + (s * 128 + kst * 16 + bLaneRow) * 272 + bLaneN;
#pragma unroll
            for (int tp = 0; tp < 4; tp++) {
                uint32_t bh[4];
                ldmx4t(bh, bAddr + tp * 32);
                mma16816(c[2 * tp],     ah, bh[0], bh[1]);
                mma16816(c[2 * tp],     al, bh[0], bh[1]);
                mma16816(c[2 * tp + 1], ah, bh[2], bh[3]);
                mma16816(c[2 * tp + 1], al, bh[2], bh[3]);
            }
        }
    }

    __syncthreads();
    {
        const float4* bh = (const float4*)g_B3h;
        float4* sh = (float4*)(sm + OFF_BH);
        for (int i = tid; i < 4224; i += 512) sh[i] = bh[i];
    }

    float s1a = 0.f, s2a = 0.f, s1b = 0.f, s2b = 0.f;
#pragma unroll
    for (int t = 0; t < 8; t++) {
        s1a += c[t][0] + c[t][1];
        s2a += c[t][0] * c[t][0] + c[t][1] * c[t][1];
        s1b += c[t][2] + c[t][3];
        s2b += c[t][2] * c[t][2] + c[t][3] * c[t][3];
    }
#pragma unroll
    for (int o = 1; o < 4; o <<= 1) {
        s1a += __shfl_xor_sync(~0u, s1a, o);
        s2a += __shfl_xor_sync(~0u, s2a, o);
        s1b += __shfl_xor_sync(~0u, s1b, o);
        s2b += __shfl_xor_sync(~0u, s2b, o);
    }
    __syncthreads();
    if ((lane & 3) == 0) {
        int r = mrow0 + (lane >> 2);
        red[r * 4 + nh * 2]           = s1a;
        red[r * 4 + nh * 2 + 1]       = s2a;
        red[(r + 8) * 4 + nh * 2]     = s1b;
        red[(r + 8) * 4 + nh * 2 + 1] = s2b;
    }
    __syncthreads();
    {
        int ra = mrow0 + (lane >> 2), rb = ra + 8;
        float mua = (red[ra * 4] + red[ra * 4 + 2]) * (1.f / 128.f);
        float vara = (red[ra * 4 + 1] + red[ra * 4 + 3]) * (1.f / 128.f) - mua * mua;
        float rsa = rsqrtf(vara + 1e-5f);
        float mub = (red[rb * 4] + red[rb * 4 + 2]) * (1.f / 128.f);
        float varb = (red[rb * 4 + 1] + red[rb * 4 + 3]) * (1.f / 128.f) - mub * mub;
        float rsb = rsqrtf(varb + 1e-5f);
        int rowa = row0 + ra, rowb = row0 + rb;
#pragma unroll
        for (int t = 0; t < 8; t++) {
            int col = nh * 64 + t * 8 + (lane & 3) * 2;
            float oax = elu1((c[t][0] - mua) * rsa * lngs[col]     + lnbs[col]);
            float oay = elu1((c[t][1] - mua) * rsa * lngs[col + 1] + lnbs[col + 1]);
            float obx = elu1((c[t][2] - mub) * rsb * lngs[col]     + lnbs[col]);
            float oby = elu1((c[t][3] - mub) * rsb * lngs[col + 1] + lnbs[col + 1]);
            if (rowa < N_NODES) *(float2*)&out_x[(size_t)rowa * DIM + col] = make_float2(oax, oay);
            if (rowb < N_NODES) *(float2*)&out_x[(size_t)rowb * DIM + col] = make_float2(obx, oby);
            uint32_t uh, ul;
            split2(oax, oay, uh, ul);
            *(uint32_t*)(sm + OFF_AH + ra * ASTR + col * 2) = uh;
            *(uint32_t*)(sm + OFF_AL + ra * ASTR + col * 2) = ul;
            split2(obx, oby, uh, ul);
            *(uint32_t*)(sm + OFF_AH + rb * ASTR + col * 2) = uh;
            *(uint32_t*)(sm + OFF_AL + rb * ASTR + col * 2) = ul;
        }
    }
    __syncthreads();

    uint32_t bLaneN2 = ((lane >> 4) & 1) * 16 + nh * 256;
    float c2[16][4];
#pragma unroll
    for (int t = 0; t < 16; t++)
#pragma unroll
        for (int q = 0; q < 4; q++) c2[t][q] = 0.f;

#pragma unroll
    for (int kst = 0; kst < 8; kst++) {
        uint32_t ah[4], al[4];
        ldmx4(ah, aAddrH + kst * 32);
        ldmx4(al, aAddrL + kst * 32);
        uint32_t bAddr = sb + OFF_BH + (kst * 16 + bLaneRow) * 528 + bLaneN2;
#pragma unroll
        for (int tp = 0; tp < 8; tp++) {
            uint32_t bh[4];
            ldmx4t(bh, bAddr + tp * 32);
            mma16816(c2[2 * tp],     ah, bh[0], bh[1]);
            mma16816(c2[2 * tp],     al, bh[0], bh[1]);
            mma16816(c2[2 * tp + 1], ah, bh[2], bh[3]);
            mma16816(c2[2 * tp + 1], al, bh[2], bh[3]);
        }
    }

    int rbase = row0 + mrow0 + (lane >> 2);
    int cbase = nh * 128 + (lane & 3) * 2;
#pragma unroll
    for (int t = 0; t < 16; t++) {
        int n0 = cbase + t * 8;
        if (rbase < N_NODES) {
            __half2 ha = __floats2half2_rn(c2[t][0], c2[t][1]);
            *(uint32_t*)&g_PQh[(size_t)rbase * 256 + n0] = *(uint32_t*)&ha;
        }
        if (rbase + 8 < N_NODES) {
            __half2 hb = __floats2half2_rn(c2[t][2], c2[t][3]);
            *(uint32_t*)&g_PQh[(size_t)(rbase + 8) * 256 + n0] = *(uint32_t*)&hb;
        }
    }
}

// ---------------- edge_out: warp per node; fp16 PQ gather; 2 edges/iter ----------------
__global__ void __launch_bounds__(256) edge_out(
    const float* __restrict__ be, const float* __restrict__ lng, const float* __restrict__ lnb,
    float* __restrict__ out_e)
{
    int gw = (blockIdx.x * 256 + threadIdx.x) >> 5;
    int lane = threadIdx.x & 31;
    if (gw >= N_NODES) return;
    int half = lane >> 4, cl = lane & 15;
    int j0 = cl * 8;

    float4 gv0 = *(const float4*)(lng + j0), gv1 = *(const float4*)(lng + j0 + 4);
    float4 bv0 = *(const float4*)(lnb + j0), bv1 = *(const float4*)(lnb + j0 + 4);
    float4 qb0, qb1;
    {
        float4 be0 = *(const float4*)(be + j0), be1 = *(const float4*)(be + j0 + 4);
        uint4 qv = *(const uint4*)&g_PQh[(size_t)gw * 256 + 128 + j0];
        float2 q01 = __half22float2(*(__half2*)&qv.x);
        float2 q23 = __half22float2(*(__half2*)&qv.y);
        float2 q45 = __half22float2(*(__half2*)&qv.z);
        float2 q67 = __half22float2(*(__half2*)&qv.w);
        qb0.x = q01.x + be0.x; qb0.y = q01.y + be0.y; qb0.z = q23.x + be0.z; qb0.w = q23.y + be0.w;
        qb1.x = q45.x + be1.x; qb1.y = q45.y + be1.y; qb1.z = q67.x + be1.z; qb1.w = q67.y + be1.w;
    }
    int beg = g_off[gw];
    int end = (gw == N_NODES - 1) ? N_EDGES : g_off[gw + 1];

    for (int b = beg; b < end; b += 32) {
        int j = b + lane;
        int sl = 0, el = 0;
        if (j < end) { int2 e2 = g_edgeE[j]; sl = e2.x; el = e2.y; }
        int cnt = min(32, end - b);
        for (int q = 0; q < cnt; q += 2) {
            int idx = q + half;
            int s_e = __shfl_sync(0xffffffffu, sl, idx);
            int e_e = __shfl_sync(0xffffffffu, el, idx);
            bool valid = idx < cnt;
            uint4 pv = *(const uint4*)&g_PQh[(size_t)s_e * 256 + j0];
            float2 p01 = __half22float2(*(__half2*)&pv.x);
            float2 p23 = __half22float2(*(__half2*)&pv.y);
            float2 p45 = __half22float2(*(__half2*)&pv.z);
            float2 p67 = __half22float2(*(__half2*)&pv.w);
            float g0 = fgelu(p01.x + qb0.x);
            float g1 = fgelu(p01.y + qb0.y);
            float g2 = fgelu(p23.x + qb0.z);
            float g3 = fgelu(p23.y + qb0.w);
            float g4 = fgelu(p45.x + qb1.x);
            float g5 = fgelu(p45.y + qb1.y);
            float g6 = fgelu(p67.x + qb1.z);
            float g7 = fgelu(p67.y + qb1.w);
            float s1 = g0 + g1 + g2 + g3 + g4 + g5 + g6 + g7;
            float s2 = g0 * g0 + g1 * g1 + g2 * g2 + g3 * g3
                     + g4 * g4 + g5 * g5 + g6 * g6 + g7 * g7;
#pragma unroll
            for (int o = 1; o < 16; o <<= 1) {
                s1 += __shfl_xor_sync(0xffffffffu, s1, o);
                s2 += __shfl_xor_sync(0xffffffffu, s2, o);
            }
            float mu = s1 * (1.f / 128.f);
            float var = s2 * (1.f / 128.f) - mu * mu;
            float rstd = rsqrtf(var + 1e-5f);
            if (valid) {
                float4 o0, o1;
                o0.x = (g0 - mu) * rstd * gv0.x + bv0.x;
                o0.y = (g1 - mu) * rstd * gv0.y + bv0.y;
                o0.z = (g2 - mu) * rstd * gv0.z + bv0.z;
                o0.w = (g3 - mu) * rstd * gv0.w + bv0.w;
                o1.x = (g4 - mu) * rstd * gv1.x + bv1.x;
                o1.y = (g5 - mu) * rstd * gv1.y + bv1.y;
                o1.z = (g6 - mu) * rstd * gv1.z + bv1.z;
                o1.w = (g7 - mu) * rstd * gv1.w + bv1.w;
                float4* op = (float4*)(out_e + (size_t)e_e * DIM + j0);
                op[0] = o0;
                op[1] = o1;
            }
        }
    }
}

extern "C" void kernel_launch(void* const* d_in, const int* in_sizes, int n_in,
                              void* d_out, int out_size)
{
    const float* x      = (const float*)d_in[0];
    const int*   ei     = (const int*)  d_in[1];
    const float* ea     = (const float*)d_in[2];
    const float* W_edge = (const float*)d_in[3];
    const float* tptr   = (const float*)d_in[4];
    const float* W1     = (const float*)d_in[5];
    const float* bng    = (const float*)d_in[6];
    const float* bnb    = (const float*)d_in[7];
    const float* W2     = (const float*)d_in[8];
    const float* lng    = (const float*)d_in[9];
    const float* lnb    = (const float*)d_in[10];
    const float* We     = (const float*)d_in[11];
    const float* be     = (const float*)d_in[12];
    const float* lneg   = (const float*)d_in[13];
    const float* lneb   = (const float*)d_in[14];

    const int* src = ei;
    const int* dst = ei + N_EDGES;

    float* out_x = (float*)d_out;
    float* out_e = out_x + (size_t)N_NODES * DIM;

    void *bnp, *b1h, *ghp, *h1p;
    cudaGetSymbolAddress(&bnp, g_bnsum);
    cudaGetSymbolAddress(&b1h, g_B1h);
    cudaGetSymbolAddress(&ghp, g_h);
    cudaGetSymbolAddress(&h1p, g_h1);

    cudaFuncSetAttribute(tc256, cudaFuncAttributeMaxDynamicSharedMemorySize, SM_TC256);
    cudaFuncSetAttribute(tc_mlp2pq, cudaFuncAttributeMaxDynamicSharedMemorySize, SM_MLP2);

    int eblocks256 = (N_EDGES + 255) / 256;
    int ablocks = (N_NODES * 32 + 255) / 256;
    int tblocks = (N_NODES + 127) / 128;

    prep_all<<<384 + 196, 256>>>(W1, We, W2);
    hist<<<eblocks256, 256>>>(dst);
    scan50k<<<1, 1024>>>();
    scatter<<<eblocks256, 256>>>(src, dst, ea);
    cudaMemsetAsync(bnp, 0, sizeof(float) * 512, 0);
    aggregate<<<ablocks, 256>>>(x, W_edge, tptr);

    tc256<<<tblocks, 512, SM_TC256>>>((const float*)ghp, (const u16*)b1h, (float*)h1p);
    bn_reduce<<<200, 256>>>();
    tc_mlp2pq<<<tblocks, 512, SM_MLP2>>>(bng, bnb, lng, lnb, out_x);
    edge_out<<<ablocks, 256>>>(be, lneg, lneb, out_e);
}

// round 17
// speedup vs baseline: 1.0266x; 1.0053x over previous
#include <cuda_runtime.h>
#include <cuda_fp16.h>
#include <math.h>
#include <stdint.h>

#define N_NODES 50000
#define N_EDGES 800000
#define DIM 128

typedef unsigned long long ull;
typedef unsigned short u16;

__device__ float g_h[(size_t)N_NODES * DIM];
__device__ float g_h1[(size_t)N_NODES * 256];
__device__ __align__(16) u16 g_PQh[(size_t)N_NODES * 256];   // fp16 [P|Q]
__device__ __align__(16) u16 g_xh[(size_t)N_NODES * DIM];    // fp16 x
__device__ float4 g_edge[(size_t)N_EDGES];                   // sorted (src_asf, ea, eid_asf, 0)
__device__ int g_cnt[N_NODES];
__device__ int g_off[N_NODES];
__device__ int g_cur[N_NODES];
__device__ float g_bnsum[512];
__device__ __align__(16) u16 g_B1h[128 * 264];
__device__ __align__(16) u16 g_B3h[128 * 264];
__device__ __align__(16) u16 g_B2h[256 * 136];

__device__ __forceinline__ uint32_t smem_u32(const void* p) {
    uint32_t a;
    asm("{ .reg .u64 t; cvta.to.shared.u64 t, %1; cvt.u32.u64 %0, t; }" : "=r"(a) : "l"(p));
    return a;
}
__device__ __forceinline__ void ldmx4(uint32_t* r, uint32_t addr) {
    asm volatile("ldmatrix.sync.aligned.m8n8.x4.shared.b16 {%0,%1,%2,%3}, [%4];"
        : "=r"(r[0]), "=r"(r[1]), "=r"(r[2]), "=r"(r[3]) : "r"(addr));
}
__device__ __forceinline__ void ldmx4t(uint32_t* r, uint32_t addr) {
    asm volatile("ldmatrix.sync.aligned.m8n8.x4.trans.shared.b16 {%0,%1,%2,%3}, [%4];"
        : "=r"(r[0]), "=r"(r[1]), "=r"(r[2]), "=r"(r[3]) : "r"(addr));
}
__device__ __forceinline__ void mma16816(float* c, const uint32_t* a, uint32_t b0, uint32_t b1) {
    asm volatile("mma.sync.aligned.m16n8k16.row.col.f32.f16.f16.f32 "
        "{%0,%1,%2,%3}, {%4,%5,%6,%7}, {%8,%9}, {%0,%1,%2,%3};"
        : "+f"(c[0]), "+f"(c[1]), "+f"(c[2]), "+f"(c[3])
        : "r"(a[0]), "r"(a[1]), "r"(a[2]), "r"(a[3]), "r"(b0), "r"(b1));
}
__device__ __forceinline__ void split2(float a, float b, uint32_t& uh, uint32_t& ul) {
    __half h0 = __float2half_rn(a), h1 = __float2half_rn(b);
    float r0 = a - __half2float(h0), r1 = b - __half2float(h1);
    __half l0 = __float2half_rn(r0), l1 = __float2half_rn(r1);
    uh = (uint32_t)(*(u16*)&h0) | ((uint32_t)(*(u16*)&h1) << 16);
    ul = (uint32_t)(*(u16*)&l0) | ((uint32_t)(*(u16*)&l1) << 16);
}
__device__ __forceinline__ float fgelu(float v) {
    float x = fabsf(v) * 0.70710678118654752f;
    float t = __fdividef(1.0f, fmaf(0.3275911f, x, 1.0f));
    float poly = t * fmaf(t, fmaf(t, fmaf(t, fmaf(t, 1.061405429f, -1.453152027f),
                  1.421413741f), -0.284496736f), 0.254829592f);
    float ex = __expf(-x * x);
    float erf_abs = fmaf(-poly, ex, 1.0f);
    float erf_v = copysignf(erf_abs, v);
    return 0.5f * v * (1.0f + erf_v);
}

#define CTRL 8192
#define ASTR 272
#define OFF_AH CTRL
#define OFF_AL (OFF_AH + 128 * ASTR)
#define OFF_BH (OFF_AL + 128 * ASTR)
#define SM_TC256 (OFF_BH + 67584)
#define SM_MLP2  (OFF_BH + 69632)

// ---------------- prep: weights fp16 + cnt zero + x fp16 convert ----------------
__global__ void __launch_bounds__(256) prep_all(
    const float* __restrict__ W1, const float* __restrict__ We, const float* __restrict__ W2,
    const float* __restrict__ x)
{
    int b = blockIdx.x;
    if (b >= 580) {       // convert x -> fp16 (1.6M float4 items)
        int i = (b - 580) * 256 + threadIdx.x;
        if (i < N_NODES * DIM / 4) {
            float4 xv = *(const float4*)&x[(size_t)i * 4];
            __half2 h0 = __floats2half2_rn(xv.x, xv.y);
            __half2 h1 = __floats2half2_rn(xv.z, xv.w);
            uint2 u = make_uint2(*(uint32_t*)&h0, *(uint32_t*)&h1);
            *(uint2*)&g_xh[(size_t)i * 4] = u;
        }
        return;
    }
    if (b >= 384) {       // zero g_cnt
        int i = (b - 384) * 256 + threadIdx.x;
        if (i < N_NODES) g_cnt[i] = 0;
        return;
    }
    int li = (b % 128) * 256 + threadIdx.x;
    if (b < 256) {
        int j = li >> 7, k = li & 127;
        float v = (b < 128) ? W1[j * 128 + k]
                : ((j < 128) ? We[j * 256 + k] : We[(j - 128) * 256 + 128 + k]);
        __half hb = __float2half_rn(v);
        u16* Bh = (b < 128) ? g_B1h : g_B3h;
        Bh[k * 264 + j] = *(u16*)&hb;
    } else {
        int j = li >> 8, k = li & 255;
        __half hb = __float2half_rn(W2[j * 256 + k]);
        g_B2h[k * 136 + j] = *(u16*)&hb;
    }
}

__global__ void __launch_bounds__(256) hist(const int* __restrict__ dst)
{
    int e = blockIdx.x * 256 + threadIdx.x;
    if (e < N_EDGES) atomicAdd(&g_cnt[dst[e]], 1);
}

__global__ void __launch_bounds__(1024) scan50k()
{
    __shared__ int wsum[32];
    __shared__ int sh_carry;
    int tid = threadIdx.x, lane = tid & 31, w = tid >> 5;
    if (tid == 0) sh_carry = 0;
    __syncthreads();
    for (int base = 0; base < N_NODES; base += 1024) {
        int i = base + tid;
        int v = (i < N_NODES) ? g_cnt[i] : 0;
        int x = v;
#pragma unroll
        for (int o = 1; o < 32; o <<= 1) { int y = __shfl_up_sync(~0u, x, o); if (lane >= o) x += y; }
        if (lane == 31) wsum[w] = x;
        __syncthreads();
        if (w == 0) {
            int s = wsum[lane];
#pragma unroll
            for (int o = 1; o < 32; o <<= 1) { int y = __shfl_up_sync(~0u, s, o); if (lane >= o) s += y; }
            wsum[lane] = s;
        }
        __syncthreads();
        int warp_excl = (w == 0) ? 0 : wsum[w - 1];
        int carry = sh_carry;
        int excl = carry + warp_excl + x - v;
        if (i < N_NODES) { g_off[i] = excl; g_cur[i] = excl; }
        __syncthreads();
        if (tid == 1023) sh_carry = carry + wsum[31];
        __syncthreads();
    }
}

__global__ void __launch_bounds__(256) scatter(
    const int* __restrict__ src, const int* __restrict__ dst, const float* __restrict__ ea)
{
    int e = blockIdx.x * 256 + threadIdx.x;
    if (e >= N_EDGES) return;
    int d = dst[e];
    int pos = atomicAdd(&g_cur[d], 1);
    g_edge[pos] = make_float4(__int_as_float(src[e]), ea[e], __int_as_float(e), 0.f);
}

// ---------------- aggregate: warp per node, fp16 x gather, prefetched ----------------
__global__ void __launch_bounds__(256) aggregate(
    const float* __restrict__ x, const float* __restrict__ W_edge, const float* __restrict__ tptr)
{
    int gw = (blockIdx.x * 256 + threadIdx.x) >> 5;
    int lane = threadIdx.x & 31;
    if (gw >= N_NODES) return;
    const float t = tptr[0];
    float4 w4 = *(const float4*)&W_edge[lane * 4];

    int beg = g_off[gw];
    int end = (gw == N_NODES - 1) ? N_EDGES : g_off[gw + 1];

    float4 aE = make_float4(0.f, 0.f, 0.f, 0.f);
    float4 aM = make_float4(0.f, 0.f, 0.f, 0.f);

    for (int b = beg; b < end; b += 32) {
        int j = b + lane;
        float2 ed = make_float2(0.f, 0.f);
        if (j < end) { float4 e4 = g_edge[j]; ed = make_float2(e4.x, e4.y); }
        int cnt = min(32, end - b);
        int s_cur = __shfl_sync(0xffffffffu, __float_as_int(ed.x), 0);
        float a_cur = __shfl_sync(0xffffffffu, ed.y, 0);
        uint2 xv = *(const uint2*)&g_xh[(size_t)s_cur * DIM + lane * 4];
        for (int q = 0; q < cnt; q++) {
            uint2 xv_n = xv;
            float a_n = a_cur;
            if (q + 1 < cnt) {
                int s_n = __shfl_sync(0xffffffffu, __float_as_int(ed.x), q + 1);
                a_n = __shfl_sync(0xffffffffu, ed.y, q + 1);
                xv_n = *(const uint2*)&g_xh[(size_t)s_n * DIM + lane * 4];
            }
            float a = a_cur;
            float2 x01 = __half22float2(*(__half2*)&xv.x);
            float2 x23 = __half22float2(*(__half2*)&xv.y);
            float m0 = fmaxf(fmaf(a, w4.x, x01.x), 0.f) + 1e-7f;
            float m1 = fmaxf(fmaf(a, w4.y, x01.y), 0.f) + 1e-7f;
            float m2 = fmaxf(fmaf(a, w4.z, x23.x), 0.f) + 1e-7f;
            float m3 = fmaxf(fmaf(a, w4.w, x23.y), 0.f) + 1e-7f;
            float e0 = __expf(m0 * t), e1 = __expf(m1 * t);
            float e2 = __expf(m2 * t), e3 = __expf(m3 * t);
            aE.x += e0; aE.y += e1; aE.z += e2; aE.w += e3;
            aM.x = fmaf(m0, e0, aM.x); aM.y = fmaf(m1, e1, aM.y);
            aM.z = fmaf(m2, e2, aM.z); aM.w = fmaf(m3, e3, aM.w);
            xv = xv_n;
            a_cur = a_n;
        }
    }
    float4 xn = *(const float4*)&x[(size_t)gw * DIM + lane * 4];
    float4 h;
    h.x = aM.x / (aE.x + 1e-16f) + xn.x;
    h.y = aM.y / (aE.y + 1e-16f) + xn.y;
    h.z = aM.z / (aE.z + 1e-16f) + xn.z;
    h.w = aM.w / (aE.w + 1e-16f) + xn.w;
    *(float4*)&g_h[(size_t)gw * DIM + lane * 4] = h;
}

__global__ void __launch_bounds__(512, 1) tc256(
    const float* __restrict__ in, const u16* __restrict__ Bh, float* __restrict__ out)
{
    extern __shared__ __align__(16) char sm[];
    uint32_t sb = smem_u32(sm);
    int tid = threadIdx.x, wid = tid >> 5, lane = tid & 31;
    int row0 = blockIdx.x * 128;

    {
        const float4* bh = (const float4*)Bh;
        float4* sh = (float4*)(sm + OFF_BH);
        for (int i = tid; i < 4224; i += 512) sh[i] = bh[i];
    }
    for (int i = tid; i < 128 * 64; i += 512) {
        int r = i >> 6, k2 = (i & 63) << 1;
        int row = row0 + r;
        float2 hv = make_float2(0.f, 0.f);
        if (row < N_NODES) hv = *(const float2*)&in[(size_t)row * 128 + k2];
        uint32_t uh, ul;
        split2(hv.x, hv.y, uh, ul);
        *(uint32_t*)(sm + OFF_AH + r * ASTR + k2 * 2) = uh;
        *(uint32_t*)(sm + OFF_AL + r * ASTR + k2 * 2) = ul;
    }
    __syncthreads();

    int mrow0 = (wid & 7) * 16, nh = wid >> 3;
    uint32_t aRow = mrow0 + (lane & 7) + ((lane >> 3) & 1) * 8;
    uint32_t aAddrH = sb + OFF_AH + aRow * ASTR + (lane >> 4) * 16;
    uint32_t aAddrL = aAddrH + (OFF_AL - OFF_AH);
    uint32_t bLaneRow = (lane & 7) + ((lane >> 3) & 1) * 8;
    uint32_t bLaneN = ((lane >> 4) & 1) * 16 + nh * 256;

    float c[16][4];
#pragma unroll
    for (int t = 0; t < 16; t++)
#pragma unroll
        for (int q = 0; q < 4; q++) c[t][q] = 0.f;

#pragma unroll
    for (int kst = 0; kst < 8; kst++) {
        uint32_t ah[4], al[4];
        ldmx4(ah, aAddrH + kst * 32);
        ldmx4(al, aAddrL + kst * 32);
        uint32_t bAddr = sb + OFF_BH + (kst * 16 + bLaneRow) * 528 + bLaneN;
#pragma unroll
        for (int tp = 0; tp < 8; tp++) {
            uint32_t bh[4];
            ldmx4t(bh, bAddr + tp * 32);
            mma16816(c[2 * tp],     ah, bh[0], bh[1]);
            mma16816(c[2 * tp],     al, bh[0], bh[1]);
            mma16816(c[2 * tp + 1], ah, bh[2], bh[3]);
            mma16816(c[2 * tp + 1], al, bh[2], bh[3]);
        }
    }

    int rbase = row0 + mrow0 + (lane >> 2);
    int cbase = nh * 128 + (lane & 3) * 2;
#pragma unroll
    for (int t = 0; t < 16; t++) {
        int n0 = cbase + t * 8;
        if (rbase < N_NODES)     *(float2*)&out[(size_t)rbase * 256 + n0]       = make_float2(c[t][0], c[t][1]);
        if (rbase + 8 < N_NODES) *(float2*)&out[(size_t)(rbase + 8) * 256 + n0] = make_float2(c[t][2], c[t][3]);
    }
}

__global__ void __launch_bounds__(256) bn_reduce()
{
    int t = threadIdx.x;
    int r0 = blockIdx.x * 250, r1 = min(r0 + 250, N_NODES);
    float s = 0.f, q = 0.f;
    for (int row = r0; row < r1; row++) {
        float v = g_h1[(size_t)row * 256 + t];
        s += v; q += v * v;
    }
    atomicAdd(&g_bnsum[t], s);
    atomicAdd(&g_bnsum[256 + t], q);
}

__device__ __forceinline__ float elu1(float v) { return v > 0.f ? v : expm1f(v); }

__global__ void __launch_bounds__(512, 1) tc_mlp2pq(
    const float* __restrict__ bng, const float* __restrict__ bnb,
    const float* __restrict__ lng, const float* __restrict__ lnb, float* __restrict__ out_x)
{
    extern __shared__ __align__(16) char sm[];
    uint32_t sb = smem_u32(sm);
    int tid = threadIdx.x, wid = tid >> 5, lane = tid & 31;
    int row0 = blockIdx.x * 128;

    float* red  = (float*)sm;
    float* lngs = (float*)(sm + 2048);
    float* lnbs = (float*)(sm + 2560);
    float* bnst = (float*)(sm + 3072);
    if (tid < 128) { lngs[tid] = lng[tid]; lnbs[tid] = lnb[tid]; }
    if (tid < 256) {
        float s = g_bnsum[tid], s2 = g_bnsum[256 + tid];
        float mu = s * (1.0f / N_NODES);
        float var = s2 * (1.0f / N_NODES) - mu * mu;
        float rstd = rsqrtf(var + 1e-5f);
        float sc = rstd * bng[tid];
        bnst[tid] = sc;
        bnst[256 + tid] = bnb[tid] - mu * sc;
    }

    {
        const float4* bh = (const float4*)g_B2h;
        float4* sh = (float4*)(sm + OFF_BH);
        for (int i = tid; i < 4352; i += 512) sh[i] = bh[i];
    }

    int mrow0 = (wid & 7) * 16, nh = wid >> 3;
    uint32_t aRow = mrow0 + (lane & 7) + ((lane >> 3) & 1) * 8;
    uint32_t aAddrH = sb + OFF_AH + aRow * ASTR + (lane >> 4) * 16;
    uint32_t aAddrL = aAddrH + (OFF_AL - OFF_AH);
    uint32_t bLaneRow = (lane & 7) + ((lane >> 3) & 1) * 8;
    uint32_t bLaneN = ((lane >> 4) & 1) * 16 + nh * 128;

    float c[8][4];
#pragma unroll
    for (int t = 0; t < 8; t++)
#pragma unroll
        for (int q = 0; q < 4; q++) c[t][q] = 0.f;

#pragma unroll
    for (int s = 0; s < 2; s++) {
        __syncthreads();
        for (int i = tid; i < 128 * 64; i += 512) {
            int r = i >> 6, k2 = (i & 63) << 1;
            int row = row0 + r;
            float v0 = 0.f, v1 = 0.f;
            if (row < N_NODES) {
                int kc = s * 128 + k2;
                float2 hv = *(const float2*)&g_h1[(size_t)row * 256 + kc];
                v0 = fmaxf(fmaf(hv.x, bnst[kc],     bnst[256 + kc]),     0.f);
                v1 = fmaxf(fmaf(hv.y, bnst[kc + 1], bnst[256 + kc + 1]), 0.f);
            }
            uint32_t uh, ul;
            split2(v0, v1, uh, ul);
            *(uint32_t*)(sm + OFF_AH + r * ASTR + k2 * 2) = uh;
            *(uint32_t*)(sm + OFF_AL + r * ASTR + k2 * 2) = ul;
        }
        __syncthreads();

#pragma unroll
        for (int kst = 0; kst < 8; kst++) {
            uint32_t ah[4], al[4];
            ldmx4(ah, aAddrH + kst * 32);
            ldmx4(al, aAddrL + kst * 32);
            uint32_t bAddr = sb + OFF_BH + (s * 128 + kst * 16 + bLaneRow) * 272 + bLaneN;
#pragma unroll
            for (int tp = 0; tp < 4; tp++) {
                uint32_t bh[4];
                ldmx4t(bh, bAddr + tp * 32);
                mma16816(c[2 * tp],     ah, bh[0], bh[1]);
                mma16816(c[2 * tp],     al, bh[0], bh[1]);
                mma16816(c[2 * tp + 1], ah, bh[2], bh[3]);
                mma16816(c[2 * tp + 1], al, bh[2], bh[3]);
            }
        }
    }

    __syncthreads();
    {
        const float4* bh = (const float4*)g_B3h;
        float4* sh = (float4*)(sm + OFF_BH);
        for (int i = tid; i < 4224; i += 512) sh[i] = bh[i];
    }

    float s1a = 0.f, s2a = 0.f, s1b = 0.f, s2b = 0.f;
#pragma unroll
    for (int t = 0; t < 8; t++) {
        s1a += c[t][0] + c[t][1];
        s2a += c[t][0] * c[t][0] + c[t][1] * c[t][1];
        s1b += c[t][2] + c[t][3];
        s2b += c[t][2] * c[t][2] + c[t][3] * c[t][3];
    }
#pragma unroll
    for (int o = 1; o < 4; o <<= 1) {
        s1a += __shfl_xor_sync(~0u, s1a, o);
        s2a += __shfl_xor_sync(~0u, s2a, o);
        s1b += __shfl_xor_sync(~0u, s1b, o);
        s2b += __shfl_xor_sync(~0u, s2b, o);
    }
    __syncthreads();
    if ((lane & 3) == 0) {
        int r = mrow0 + (lane >> 2);
        red[r * 4 + nh * 2]           = s1a;
        red[r * 4 + nh * 2 + 1]       = s2a;
        red[(r + 8) * 4 + nh * 2]     = s1b;
        red[(r + 8) * 4 + nh * 2 + 1] = s2b;
    }
    __syncthreads();
    {
        int ra = mrow0 + (lane >> 2), rb = ra + 8;
        float mua = (red[ra * 4] + red[ra * 4 + 2]) * (1.f / 128.f);
        float vara = (red[ra * 4 + 1] + red[ra * 4 + 3]) * (1.f / 128.f) - mua * mua;
        float rsa = rsqrtf(vara + 1e-5f);
        float mub = (red[rb * 4] + red[rb * 4 + 2]) * (1.f / 128.f);
        float varb = (red[rb * 4 + 1] + red[rb * 4 + 3]) * (1.f / 128.f) - mub * mub;
        float rsb = rsqrtf(varb + 1e-5f);
        int rowa = row0 + ra, rowb = row0 + rb;
#pragma unroll
        for (int t = 0; t < 8; t++) {
            int col = nh * 64 + t * 8 + (lane & 3) * 2;
            float oax = elu1((c[t][0] - mua) * rsa * lngs[col]     + lnbs[col]);
            float oay = elu1((c[t][1] - mua) * rsa * lngs[col + 1] + lnbs[col + 1]);
            float obx = elu1((c[t][2] - mub) * rsb * lngs[col]     + lnbs[col]);
            float oby = elu1((c[t][3] - mub) * rsb * lngs[col + 1] + lnbs[col + 1]);
            if (rowa < N_NODES) *(float2*)&out_x[(size_t)rowa * DIM + col] = make_float2(oax, oay);
            if (rowb < N_NODES) *(float2*)&out_x[(size_t)rowb * DIM + col] = make_float2(obx, oby);
            uint32_t uh, ul;
            split2(oax, oay, uh, ul);
            *(uint32_t*)(sm + OFF_AH + ra * ASTR + col * 2) = uh;
            *(uint32_t*)(sm + OFF_AL + ra * ASTR + col * 2) = ul;
            split2(obx, oby, uh, ul);
            *(uint32_t*)(sm + OFF_AH + rb * ASTR + col * 2) = uh;
            *(uint32_t*)(sm + OFF_AL + rb * ASTR + col * 2) = ul;
        }
    }
    __syncthreads();

    uint32_t bLaneN2 = ((lane >> 4) & 1) * 16 + nh * 256;
    float c2[16][4];
#pragma unroll
    for (int t = 0; t < 16; t++)
#pragma unroll
        for (int q = 0; q < 4; q++) c2[t][q] = 0.f;

#pragma unroll
    for (int kst = 0; kst < 8; kst++) {
        uint32_t ah[4], al[4];
        ldmx4(ah, aAddrH + kst * 32);
        ldmx4(al, aAddrL + kst * 32);
        uint32_t bAddr = sb + OFF_BH + (kst * 16 + bLaneRow) * 528 + bLaneN2;
#pragma unroll
        for (int tp = 0; tp < 8; tp++) {
            uint32_t bh[4];
            ldmx4t(bh, bAddr + tp * 32);
            mma16816(c2[2 * tp],     ah, bh[0], bh[1]);
            mma16816(c2[2 * tp],     al, bh[0], bh[1]);
            mma16816(c2[2 * tp + 1], ah, bh[2], bh[3]);
            mma16816(c2[2 * tp + 1], al, bh[2], bh[3]);
        }
    }

    int rbase = row0 + mrow0 + (lane >> 2);
    int cbase = nh * 128 + (lane & 3) * 2;
#pragma unroll
    for (int t = 0; t < 16; t++) {
        int n0 = cbase + t * 8;
        if (rbase < N_NODES) {
            __half2 ha = __floats2half2_rn(c2[t][0], c2[t][1]);
            *(uint32_t*)&g_PQh[(size_t)rbase * 256 + n0] = *(uint32_t*)&ha;
        }
        if (rbase + 8 < N_NODES) {
            __half2 hb = __floats2half2_rn(c2[t][2], c2[t][3]);
            *(uint32_t*)&g_PQh[(size_t)(rbase + 8) * 256 + n0] = *(uint32_t*)&hb;
        }
    }
}

// ---------------- edge_out: warp per node; fp16 PQ gather; 2 edges/iter ----------------
__global__ void __launch_bounds__(256) edge_out(
    const float* __restrict__ be, const float* __restrict__ lng, const float* __restrict__ lnb,
    float* __restrict__ out_e)
{
    int gw = (blockIdx.x * 256 + threadIdx.x) >> 5;
    int lane = threadIdx.x & 31;
    if (gw >= N_NODES) return;
    int half = lane >> 4, cl = lane & 15;
    int j0 = cl * 8;

    float4 gv0 = *(const float4*)(lng + j0), gv1 = *(const float4*)(lng + j0 + 4);
    float4 bv0 = *(const float4*)(lnb + j0), bv1 = *(const float4*)(lnb + j0 + 4);
    float4 qb0, qb1;
    {
        float4 be0 = *(const float4*)(be + j0), be1 = *(const float4*)(be + j0 + 4);
        uint4 qv = *(const uint4*)&g_PQh[(size_t)gw * 256 + 128 + j0];
        float2 q01 = __half22float2(*(__half2*)&qv.x);
        float2 q23 = __half22float2(*(__half2*)&qv.y);
        float2 q45 = __half22float2(*(__half2*)&qv.z);
        float2 q67 = __half22float2(*(__half2*)&qv.w);
        qb0.x = q01.x + be0.x; qb0.y = q01.y + be0.y; qb0.z = q23.x + be0.z; qb0.w = q23.y + be0.w;
        qb1.x = q45.x + be1.x; qb1.y = q45.y + be1.y; qb1.z = q67.x + be1.z; qb1.w = q67.y + be1.w;
    }
    int beg = g_off[gw];
    int end = (gw == N_NODES - 1) ? N_EDGES : g_off[gw + 1];

    for (int b = beg; b < end; b += 32) {
        int j = b + lane;
        int sl = 0, el = 0;
        if (j < end) { float4 e4 = g_edge[j]; sl = __float_as_int(e4.x); el = __float_as_int(e4.z); }
        int cnt = min(32, end - b);
        for (int q = 0; q < cnt; q += 2) {
            int idx = q + half;
            int s_e = __shfl_sync(0xffffffffu, sl, idx);
            int e_e = __shfl_sync(0xffffffffu, el, idx);
            bool valid = idx < cnt;
            uint4 pv = *(const uint4*)&g_PQh[(size_t)s_e * 256 + j0];
            float2 p01 = __half22float2(*(__half2*)&pv.x);
            float2 p23 = __half22float2(*(__half2*)&pv.y);
            float2 p45 = __half22float2(*(__half2*)&pv.z);
            float2 p67 = __half22float2(*(__half2*)&pv.w);
            float g0 = fgelu(p01.x + qb0.x);
            float g1 = fgelu(p01.y + qb0.y);
            float g2 = fgelu(p23.x + qb0.z);
            float g3 = fgelu(p23.y + qb0.w);
            float g4 = fgelu(p45.x + qb1.x);
            float g5 = fgelu(p45.y + qb1.y);
            float g6 = fgelu(p67.x + qb1.z);
            float g7 = fgelu(p67.y + qb1.w);
            float s1 = g0 + g1 + g2 + g3 + g4 + g5 + g6 + g7;
            float s2 = g0 * g0 + g1 * g1 + g2 * g2 + g3 * g3
                     + g4 * g4 + g5 * g5 + g6 * g6 + g7 * g7;
#pragma unroll
            for (int o = 1; o < 16; o <<= 1) {
                s1 += __shfl_xor_sync(0xffffffffu, s1, o);
                s2 += __shfl_xor_sync(0xffffffffu, s2, o);
            }
            float mu = s1 * (1.f / 128.f);
            float var = s2 * (1.f / 128.f) - mu * mu;
            float rstd = rsqrtf(var + 1e-5f);
            if (valid) {
                float4 o0, o1;
                o0.x = (g0 - mu) * rstd * gv0.x + bv0.x;
                o0.y = (g1 - mu) * rstd * gv0.y + bv0.y;
                o0.z = (g2 - mu) * rstd * gv0.z + bv0.z;
                o0.w = (g3 - mu) * rstd * gv0.w + bv0.w;
                o1.x = (g4 - mu) * rstd * gv1.x + bv1.x;
                o1.y = (g5 - mu) * rstd * gv1.y + bv1.y;
                o1.z = (g6 - mu) * rstd * gv1.z + bv1.z;
                o1.w = (g7 - mu) * rstd * gv1.w + bv1.w;
                float4* op = (float4*)(out_e + (size_t)e_e * DIM + j0);
                op[0] = o0;
                op[1] = o1;
            }
        }
    }
}

extern "C" void kernel_launch(void* const* d_in, const int* in_sizes, int n_in,
                              void* d_out, int out_size)
{
    const float* x      = (const float*)d_in[0];
    const int*   ei     = (const int*)  d_in[1];
    const float* ea     = (const float*)d_in[2];
    const float* W_edge = (const float*)d_in[3];
    const float* tptr   = (const float*)d_in[4];
    const float* W1     = (const float*)d_in[5];
    const float* bng    = (const float*)d_in[6];
    const float* bnb    = (const float*)d_in[7];
    const float* W2     = (const float*)d_in[8];
    const float* lng    = (const float*)d_in[9];
    const float* lnb    = (const float*)d_in[10];
    const float* We     = (const float*)d_in[11];
    const float* be     = (const float*)d_in[12];
    const float* lneg   = (const float*)d_in[13];
    const float* lneb   = (const float*)d_in[14];

    const int* src = ei;
    const int* dst = ei + N_EDGES;

    float* out_x = (float*)d_out;
    float* out_e = out_x + (size_t)N_NODES * DIM;

    void *bnp, *b1h, *ghp, *h1p;
    cudaGetSymbolAddress(&bnp, g_bnsum);
    cudaGetSymbolAddress(&b1h, g_B1h);
    cudaGetSymbolAddress(&ghp, g_h);
    cudaGetSymbolAddress(&h1p, g_h1);

    cudaFuncSetAttribute(tc256, cudaFuncAttributeMaxDynamicSharedMemorySize, SM_TC256);
    cudaFuncSetAttribute(tc_mlp2pq, cudaFuncAttributeMaxDynamicSharedMemorySize, SM_MLP2);

    int eblocks256 = (N_EDGES + 255) / 256;
    int ablocks = (N_NODES * 32 + 255) / 256;
    int tblocks = (N_NODES + 127) / 128;
    int xblocks = (N_NODES * DIM / 4 + 255) / 256;   // 6250

    prep_all<<<580 + xblocks, 256>>>(W1, We, W2, x);   // weights + cnt zero + x fp16
    hist<<<eblocks256, 256>>>(dst);
    scan50k<<<1, 1024>>>();
    scatter<<<eblocks256, 256>>>(src, dst, ea);
    cudaMemsetAsync(bnp, 0, sizeof(float) * 512, 0);
    aggregate<<<ablocks, 256>>>(x, W_edge, tptr);

    tc256<<<tblocks, 512, SM_TC256>>>((const float*)ghp, (const u16*)b1h, (float*)h1p);
    bn_reduce<<<200, 256>>>();
    tc_mlp2pq<<<tblocks, 512, SM_MLP2>>>(bng, bnb, lng, lnb, out_x);
    edge_out<<<ablocks, 256>>>(be, lneg, lneb, out_e);
}